// round 7
// baseline (speedup 1.0000x reference)
#include <cuda_runtime.h>
#include <cstdint>

#define NHEADS 16
#define B_     2
#define N_     2048
#define C_     1024
#define HD     64

// Scratch for rotated/projected Q, K, V in [B,H,N,hd] layout. 3 x 16 MB.
__device__ float g_scratch[3][B_ * NHEADS * N_ * HD];
// g_bad[0]: proj tf32 output wrong; g_bad[1]: attn tf32 output wrong.
__device__ int g_bad[2];

// ---------------------------------------------------------------------------
// tf32 helpers
// ---------------------------------------------------------------------------
__device__ __forceinline__ uint32_t tf32_bits(float x) {
    uint32_t r;
    asm("cvt.rna.tf32.f32 %0, %1;" : "=r"(r) : "f"(x));
    return r;
}
__device__ __forceinline__ float to_tf32(float x) {
    return __uint_as_float(tf32_bits(x));
}
__device__ __forceinline__ float2 tf32_split(float x) {
    float hi = to_tf32(x);
    float lo = to_tf32(x - hi);
    return make_float2(hi, lo);
}
__device__ __forceinline__ void mma_tf32(float* d,
                                         const uint32_t* a,
                                         const uint32_t* b,
                                         const float* c) {
    asm volatile(
        "mma.sync.aligned.m16n8k8.row.col.f32.tf32.tf32.f32 "
        "{%0,%1,%2,%3}, {%4,%5,%6,%7}, {%8,%9}, {%10,%11,%12,%13};"
        : "=f"(d[0]), "=f"(d[1]), "=f"(d[2]), "=f"(d[3])
        : "r"(a[0]), "r"(a[1]), "r"(a[2]), "r"(a[3]),
          "r"(b[0]), "r"(b[1]),
          "f"(c[0]), "f"(c[1]), "f"(c[2]), "f"(c[3]));
}
__device__ __forceinline__ uint32_t f2u(float x) { return __float_as_uint(x); }

// ===========================================================================
// Flag reset
// ===========================================================================
__global__ void reset_kernel() {
    if (threadIdx.x < 2) g_bad[threadIdx.x] = 0;
}

// ===========================================================================
// TF32 projection (3x compensated), CTA 128x128, z selects {Q,K,V}
// ===========================================================================
__global__ __launch_bounds__(256, 2) void proj_tf32_kernel(
    const float* __restrict__ Xq, const float* __restrict__ Xk,
    const float* __restrict__ Xv,
    const float* __restrict__ Wq, const float* __restrict__ Wk,
    const float* __restrict__ Wv,
    const float* __restrict__ bq, const float* __restrict__ bk,
    const float* __restrict__ bv,
    const float* __restrict__ cosT, const float* __restrict__ sinT)
{
    extern __shared__ float2 smem2[];
    float2* As = smem2;              // [128][36]
    float2* Bs = As + 128 * 36;      // [128][36]

    const int which = blockIdx.z;
    const float* __restrict__ X    = which == 0 ? Xq : (which == 1 ? Xk : Xv);
    const float* __restrict__ W    = which == 0 ? Wq : (which == 1 ? Wk : Wv);
    const float* __restrict__ bias = which == 0 ? bq : (which == 1 ? bk : bv);
    const int doRope = (which != 2);
    float* __restrict__ outp = g_scratch[which];

    const int tid  = threadIdx.x;
    const int wid  = tid >> 5;
    const int lane = tid & 31;
    const int r    = lane >> 2;
    const int c    = lane & 3;
    const int wm   = wid & 1;
    const int wn   = wid >> 1;

    const int m0 = blockIdx.y * 128;
    const int n0 = blockIdx.x * 128;

    const int lrow = tid >> 3;
    const int lkf  = (tid & 7) * 4;

    float acc[4][4][4];
#pragma unroll
    for (int i = 0; i < 4; i++)
#pragma unroll
        for (int j = 0; j < 4; j++)
#pragma unroll
            for (int t = 0; t < 4; t++) acc[i][j][t] = 0.f;

    for (int kc = 0; kc < C_; kc += 32) {
#pragma unroll
        for (int p = 0; p < 4; p++) {
            const int row = lrow + p * 32;
            float4 av  = *(const float4*)(X + (size_t)(m0 + row) * C_ + kc + lkf);
            float4 bv4 = *(const float4*)(W + (size_t)(n0 + row) * C_ + kc + lkf);
            As[row * 36 + lkf + 0] = tf32_split(av.x);
            As[row * 36 + lkf + 1] = tf32_split(av.y);
            As[row * 36 + lkf + 2] = tf32_split(av.z);
            As[row * 36 + lkf + 3] = tf32_split(av.w);
            Bs[row * 36 + lkf + 0] = tf32_split(bv4.x);
            Bs[row * 36 + lkf + 1] = tf32_split(bv4.y);
            Bs[row * 36 + lkf + 2] = tf32_split(bv4.z);
            Bs[row * 36 + lkf + 3] = tf32_split(bv4.w);
        }
        __syncthreads();

#pragma unroll
        for (int ks = 0; ks < 4; ks++) {
            const int kb = ks * 8;
            uint32_t bhi[4][2], blo[4][2];
#pragma unroll
            for (int nf = 0; nf < 4; nf++) {
                const int nrow = wn * 32 + nf * 8 + r;
                float2 b0 = Bs[nrow * 36 + kb + c];
                float2 b1 = Bs[nrow * 36 + kb + c + 4];
                bhi[nf][0] = f2u(b0.x); blo[nf][0] = f2u(b0.y);
                bhi[nf][1] = f2u(b1.x); blo[nf][1] = f2u(b1.y);
            }
#pragma unroll
            for (int mf = 0; mf < 4; mf++) {
                const int mrow = wm * 64 + mf * 16 + r;
                float2 a0 = As[mrow * 36 + kb + c];
                float2 a1 = As[(mrow + 8) * 36 + kb + c];
                float2 a2 = As[mrow * 36 + kb + c + 4];
                float2 a3 = As[(mrow + 8) * 36 + kb + c + 4];
                uint32_t ahi[4] = {f2u(a0.x), f2u(a1.x), f2u(a2.x), f2u(a3.x)};
                uint32_t alo[4] = {f2u(a0.y), f2u(a1.y), f2u(a2.y), f2u(a3.y)};
#pragma unroll
                for (int nf = 0; nf < 4; nf++) {
                    mma_tf32(acc[mf][nf], ahi, bhi[nf], acc[mf][nf]);
                    mma_tf32(acc[mf][nf], ahi, blo[nf], acc[mf][nf]);
                    mma_tf32(acc[mf][nf], alo, bhi[nf], acc[mf][nf]);
                }
            }
        }
        __syncthreads();
    }

#pragma unroll
    for (int nf = 0; nf < 4; nf++) {
        const int col = n0 + wn * 32 + nf * 8 + 2 * c;
        const int h = col >> 6;
        const int dbase = col & 63;
        const int f = dbase >> 1;
        const float bias0 = bias[col];
        const float bias1 = bias[col + 1];
#pragma unroll
        for (int mf = 0; mf < 4; mf++) {
#pragma unroll
            for (int half = 0; half < 2; half++) {
                const int m = m0 + wm * 64 + mf * 16 + r + half * 8;
                const int bidx = m >> 11;
                const int n = m & 2047;
                float v0 = acc[mf][nf][half * 2 + 0] + bias0;
                float v1 = acc[mf][nf][half * 2 + 1] + bias1;
                if (doRope) {
                    const float cs = cosT[n * 32 + f];
                    const float sn = sinT[n * 32 + f];
                    const float rr = v0, ri = v1;
                    v0 = rr * cs - ri * sn;
                    v1 = rr * sn + ri * cs;
                }
                *(float2*)&outp[(((size_t)bidx * NHEADS + h) * N_ + n) * HD + dbase] =
                    make_float2(v0, v1);
            }
        }
    }
}

// ===========================================================================
// Proj checker: 3 blocks (one per which) x 256 samples; fp32 recompute.
// ===========================================================================
__global__ void proj_check_kernel(
    const float* __restrict__ Xq, const float* __restrict__ Xk,
    const float* __restrict__ Xv,
    const float* __restrict__ Wq, const float* __restrict__ Wk,
    const float* __restrict__ Wv,
    const float* __restrict__ bq, const float* __restrict__ bk,
    const float* __restrict__ bv,
    const float* __restrict__ cosT, const float* __restrict__ sinT)
{
    const int which = blockIdx.x;
    const float* __restrict__ X    = which == 0 ? Xq : (which == 1 ? Xk : Xv);
    const float* __restrict__ W    = which == 0 ? Wq : (which == 1 ? Wk : Wv);
    const float* __restrict__ bias = which == 0 ? bq : (which == 1 ? bk : bv);

    const int t = threadIdx.x;
    const int m   = (t * 521 + which * 1365) & 4095;
    const int col = (t * 1031 + which * 342) & 1022;   // even, < 1024

    float s0a = 0.f, s0b = 0.f, s1a = 0.f, s1b = 0.f;
    const float* Xr = X + (size_t)m * C_;
    const float* W0 = W + (size_t)col * C_;
    const float* W1 = W + (size_t)(col + 1) * C_;
    for (int kk = 0; kk < C_; kk += 4) {
        float4 xv = *(const float4*)(Xr + kk);
        float4 w0 = *(const float4*)(W0 + kk);
        float4 w1 = *(const float4*)(W1 + kk);
        s0a += xv.x * w0.x + xv.y * w0.y;
        s0b += xv.z * w0.z + xv.w * w0.w;
        s1a += xv.x * w1.x + xv.y * w1.y;
        s1b += xv.z * w1.z + xv.w * w1.w;
    }
    float s0 = s0a + s0b + bias[col];
    float s1 = s1a + s1b + bias[col + 1];

    const int n = m & 2047, b = m >> 11, h = col >> 6, d = col & 63;
    if (which != 2) {
        const float cs = cosT[n * 32 + (d >> 1)];
        const float sn = sinT[n * 32 + (d >> 1)];
        const float rr = s0, ri = s1;
        s0 = rr * cs - ri * sn;
        s1 = rr * sn + ri * cs;
    }
    const float g0 = g_scratch[which][(((size_t)b * NHEADS + h) * N_ + n) * HD + d];
    const float g1 = g_scratch[which][(((size_t)b * NHEADS + h) * N_ + n) * HD + d + 1];
    // inverted compare catches NaN
    const bool ok0 = fabsf(g0 - s0) <= 5e-3f * (fabsf(s0) + 1.f);
    const bool ok1 = fabsf(g1 - s1) <= 5e-3f * (fabsf(s1) + 1.f);
    if (!(ok0 && ok1)) atomicOr(&g_bad[0], 1);
}

// ===========================================================================
// Fallback projection (round-2 FFMA, known good), gated on g_bad[0].
// ===========================================================================
__global__ __launch_bounds__(256) void proj_fix_kernel(
    const float* __restrict__ X, const float* __restrict__ W,
    const float* __restrict__ bias,
    const float* __restrict__ cosT, const float* __restrict__ sinT,
    int which, int doRope)
{
    if (g_bad[0] == 0) return;

    __shared__ float As[16][68];
    __shared__ float Bs[16][68];

    float* __restrict__ outp = g_scratch[which];

    const int tid = threadIdx.x;
    const int tx = tid & 15;
    const int ty = tid >> 4;
    const int m0 = blockIdx.y * 64;
    const int n0 = blockIdx.x * 64;

    const int lr = tid >> 2;
    const int lk = (tid & 3) * 4;

    const float* Arow = X + (size_t)(m0 + lr) * C_;
    const float* Brow = W + (size_t)(n0 + lr) * C_;

    float acc[4][4] = {};

    for (int k0 = 0; k0 < C_; k0 += 16) {
        float4 av = *(const float4*)(Arow + k0 + lk);
        float4 bv4 = *(const float4*)(Brow + k0 + lk);
        As[lk + 0][lr] = av.x; As[lk + 1][lr] = av.y;
        As[lk + 2][lr] = av.z; As[lk + 3][lr] = av.w;
        Bs[lk + 0][lr] = bv4.x; Bs[lk + 1][lr] = bv4.y;
        Bs[lk + 2][lr] = bv4.z; Bs[lk + 3][lr] = bv4.w;
        __syncthreads();
#pragma unroll
        for (int kk = 0; kk < 16; kk++) {
            float4 a = *(const float4*)&As[kk][ty * 4];
            float4 b = *(const float4*)&Bs[kk][tx * 4];
            acc[0][0] += a.x * b.x; acc[0][1] += a.x * b.y;
            acc[0][2] += a.x * b.z; acc[0][3] += a.x * b.w;
            acc[1][0] += a.y * b.x; acc[1][1] += a.y * b.y;
            acc[1][2] += a.y * b.z; acc[1][3] += a.y * b.w;
            acc[2][0] += a.z * b.x; acc[2][1] += a.z * b.y;
            acc[2][2] += a.z * b.z; acc[2][3] += a.z * b.w;
            acc[3][0] += a.w * b.x; acc[3][1] += a.w * b.y;
            acc[3][2] += a.w * b.z; acc[3][3] += a.w * b.w;
        }
        __syncthreads();
    }

    const int col0 = n0 + tx * 4;
    const int h = col0 >> 6;
    const int dbase = col0 & 63;
    const float b0 = bias[col0 + 0];
    const float b1 = bias[col0 + 1];
    const float b2 = bias[col0 + 2];
    const float b3 = bias[col0 + 3];

#pragma unroll
    for (int i = 0; i < 4; i++) {
        const int m = m0 + ty * 4 + i;
        const int bidx = m >> 11;
        const int n = m & 2047;
        float v0 = acc[i][0] + b0;
        float v1 = acc[i][1] + b1;
        float v2 = acc[i][2] + b2;
        float v3 = acc[i][3] + b3;
        if (doRope) {
            const int f0 = dbase >> 1;
            const int f1 = f0 + 1;
            const float c0 = cosT[n * 32 + f0], s0 = sinT[n * 32 + f0];
            const float c1 = cosT[n * 32 + f1], s1 = sinT[n * 32 + f1];
            float r0 = v0, i0 = v1, r1 = v2, i1 = v3;
            v0 = r0 * c0 - i0 * s0;
            v1 = r0 * s0 + i0 * c0;
            v2 = r1 * c1 - i1 * s1;
            v3 = r1 * s1 + i1 * c1;
        }
        float4 o4 = make_float4(v0, v1, v2, v3);
        *(float4*)&outp[(((size_t)bidx * NHEADS + h) * N_ + n) * HD + dbase] = o4;
    }
}

// ===========================================================================
// TF32 flash-attention (3x QK^T, 1x PV)
// ===========================================================================
__global__ __launch_bounds__(256) void attn_tf32_kernel(float* __restrict__ out)
{
    extern __shared__ char smraw[];
    float2* Qs = (float2*)smraw;             // [128][36]
    float2* Ks = Qs + 128 * 36;              // [64][36]
    float*  Vs = (float*)(Ks + 64 * 36);     // [64][72]
    float*  Ps = Vs + 64 * 72;               // [128][72]

    const int tid  = threadIdx.x;
    const int wid  = tid >> 5;
    const int lane = tid & 31;
    const int r    = lane >> 2;
    const int c    = lane & 3;

    const int bh = blockIdx.y;
    const int q0 = blockIdx.x * 128;

    const float* __restrict__ Qg = g_scratch[0] + ((size_t)bh * N_ + q0) * HD;
    const float* __restrict__ Kg = g_scratch[1] + (size_t)bh * N_ * HD;
    const float* __restrict__ Vg = g_scratch[2] + (size_t)bh * N_ * HD;

#pragma unroll
    for (int i = 0; i < 8; i++) {
        const int idx = tid + i * 256;
        const int row = idx >> 4;
        const int d0 = (idx & 15) * 4;
        float4 qv = *(const float4*)(Qg + row * HD + d0);
        Qs[row * 36 + d0 + 0] = tf32_split(qv.x * 0.125f);
        Qs[row * 36 + d0 + 1] = tf32_split(qv.y * 0.125f);
        Qs[row * 36 + d0 + 2] = tf32_split(qv.z * 0.125f);
        Qs[row * 36 + d0 + 3] = tf32_split(qv.w * 0.125f);
    }

    float oacc[8][4];
#pragma unroll
    for (int n = 0; n < 8; n++)
#pragma unroll
        for (int t = 0; t < 4; t++) oacc[n][t] = 0.f;
    float mrow0 = -1e30f, mrow1 = -1e30f;
    float lrow0 = 0.f, lrow1 = 0.f;

    const int qrow = wid * 16 + r;

    for (int kt = 0; kt < N_ / 64; kt++) {
        __syncthreads();
        const float* Kt = Kg + (size_t)kt * 64 * HD;
        const float* Vt = Vg + (size_t)kt * 64 * HD;
#pragma unroll
        for (int i = 0; i < 4; i++) {
            const int idx = tid + i * 256;
            const int row = idx >> 4;
            const int d0 = (idx & 15) * 4;
            float4 kv = *(const float4*)(Kt + row * HD + d0);
            Ks[row * 36 + d0 + 0] = tf32_split(kv.x);
            Ks[row * 36 + d0 + 1] = tf32_split(kv.y);
            Ks[row * 36 + d0 + 2] = tf32_split(kv.z);
            Ks[row * 36 + d0 + 3] = tf32_split(kv.w);
            float4 vv = *(const float4*)(Vt + row * HD + d0);
            Vs[row * 72 + d0 + 0] = to_tf32(vv.x);
            Vs[row * 72 + d0 + 1] = to_tf32(vv.y);
            Vs[row * 72 + d0 + 2] = to_tf32(vv.z);
            Vs[row * 72 + d0 + 3] = to_tf32(vv.w);
        }
        __syncthreads();

        float sacc[8][4];
#pragma unroll
        for (int n = 0; n < 8; n++)
#pragma unroll
            for (int t = 0; t < 4; t++) sacc[n][t] = 0.f;

#pragma unroll
        for (int kf = 0; kf < 8; kf++) {
            const int d = kf * 8 + c;
            float2 a0 = Qs[qrow * 36 + d];
            float2 a1 = Qs[(qrow + 8) * 36 + d];
            float2 a2 = Qs[qrow * 36 + d + 4];
            float2 a3 = Qs[(qrow + 8) * 36 + d + 4];
            uint32_t ahi[4] = {f2u(a0.x), f2u(a1.x), f2u(a2.x), f2u(a3.x)};
            uint32_t alo[4] = {f2u(a0.y), f2u(a1.y), f2u(a2.y), f2u(a3.y)};
#pragma unroll
            for (int n = 0; n < 8; n++) {
                const int key = n * 8 + r;
                float2 b0 = Ks[key * 36 + d];
                float2 b1 = Ks[key * 36 + d + 4];
                uint32_t bhi[2] = {f2u(b0.x), f2u(b1.x)};
                uint32_t blo[2] = {f2u(b0.y), f2u(b1.y)};
                mma_tf32(sacc[n], ahi, bhi, sacc[n]);
                mma_tf32(sacc[n], ahi, blo, sacc[n]);
                mma_tf32(sacc[n], alo, bhi, sacc[n]);
            }
        }

        float tmax0 = -1e30f, tmax1 = -1e30f;
#pragma unroll
        for (int n = 0; n < 8; n++) {
            tmax0 = fmaxf(tmax0, fmaxf(sacc[n][0], sacc[n][1]));
            tmax1 = fmaxf(tmax1, fmaxf(sacc[n][2], sacc[n][3]));
        }
        tmax0 = fmaxf(tmax0, __shfl_xor_sync(0xffffffffu, tmax0, 1));
        tmax0 = fmaxf(tmax0, __shfl_xor_sync(0xffffffffu, tmax0, 2));
        tmax1 = fmaxf(tmax1, __shfl_xor_sync(0xffffffffu, tmax1, 1));
        tmax1 = fmaxf(tmax1, __shfl_xor_sync(0xffffffffu, tmax1, 2));

        const float mn0 = fmaxf(mrow0, tmax0);
        const float mn1 = fmaxf(mrow1, tmax1);
        const float fac0 = __expf(mrow0 - mn0);
        const float fac1 = __expf(mrow1 - mn1);
        mrow0 = mn0; mrow1 = mn1;

        float rs0 = 0.f, rs1 = 0.f;
#pragma unroll
        for (int n = 0; n < 8; n++) {
            sacc[n][0] = __expf(sacc[n][0] - mn0);
            sacc[n][1] = __expf(sacc[n][1] - mn0);
            sacc[n][2] = __expf(sacc[n][2] - mn1);
            sacc[n][3] = __expf(sacc[n][3] - mn1);
            rs0 += sacc[n][0] + sacc[n][1];
            rs1 += sacc[n][2] + sacc[n][3];
        }
        rs0 += __shfl_xor_sync(0xffffffffu, rs0, 1);
        rs0 += __shfl_xor_sync(0xffffffffu, rs0, 2);
        rs1 += __shfl_xor_sync(0xffffffffu, rs1, 1);
        rs1 += __shfl_xor_sync(0xffffffffu, rs1, 2);
        lrow0 = lrow0 * fac0 + rs0;
        lrow1 = lrow1 * fac1 + rs1;

#pragma unroll
        for (int n = 0; n < 8; n++) {
            oacc[n][0] *= fac0; oacc[n][1] *= fac0;
            oacc[n][2] *= fac1; oacc[n][3] *= fac1;
        }

#pragma unroll
        for (int n = 0; n < 8; n++) {
            const int col = n * 8 + 2 * c;
            Ps[qrow * 72 + col]           = to_tf32(sacc[n][0]);
            Ps[qrow * 72 + col + 1]       = to_tf32(sacc[n][1]);
            Ps[(qrow + 8) * 72 + col]     = to_tf32(sacc[n][2]);
            Ps[(qrow + 8) * 72 + col + 1] = to_tf32(sacc[n][3]);
        }
        __syncwarp();

#pragma unroll
        for (int kf = 0; kf < 8; kf++) {
            const int kcol = kf * 8 + c;
            uint32_t pa[4];
            pa[0] = f2u(Ps[qrow * 72 + kcol]);
            pa[1] = f2u(Ps[(qrow + 8) * 72 + kcol]);
            pa[2] = f2u(Ps[qrow * 72 + kcol + 4]);
            pa[3] = f2u(Ps[(qrow + 8) * 72 + kcol + 4]);
#pragma unroll
            for (int n = 0; n < 8; n++) {
                uint32_t bb[2];
                const int d = n * 8 + r;
                bb[0] = f2u(Vs[(kf * 8 + c) * 72 + d]);
                bb[1] = f2u(Vs[(kf * 8 + c + 4) * 72 + d]);
                mma_tf32(oacc[n], pa, bb, oacc[n]);
            }
        }
    }

    const int b = bh >> 4;
    const int h = bh & 15;
    const float inv0 = 1.0f / lrow0;
    const float inv1 = 1.0f / lrow1;
    const int row0 = q0 + wid * 16 + r;
#pragma unroll
    for (int n = 0; n < 8; n++) {
        const int d = n * 8 + 2 * c;
        *(float2*)&out[((size_t)b * N_ + row0) * C_ + h * HD + d] =
            make_float2(oacc[n][0] * inv0, oacc[n][1] * inv0);
        *(float2*)&out[((size_t)b * N_ + row0 + 8) * C_ + h * HD + d] =
            make_float2(oacc[n][2] * inv1, oacc[n][3] * inv1);
    }
}

// ===========================================================================
// Attention checker: 16 blocks x 8 warps = 128 sampled rows; fp32 recompute.
// Each warp: lanes split keys (stride 32), online softmax, butterfly merge.
// ===========================================================================
__global__ __launch_bounds__(256) void attn_check_kernel(const float* __restrict__ out)
{
    const int wid  = threadIdx.x >> 5;
    const int lane = threadIdx.x & 31;
    const int s  = blockIdx.x * 8 + wid;     // 0..127
    const int bh = s & 31;
    const int q  = (s * 997 + 13) & 2047;

    const float* Qr = g_scratch[0] + ((size_t)bh * N_ + q) * HD;
    const float* Kg = g_scratch[1] + (size_t)bh * N_ * HD;
    const float* Vg = g_scratch[2] + (size_t)bh * N_ * HD;

    float qreg[HD];
#pragma unroll
    for (int d = 0; d < HD; d++) qreg[d] = Qr[d] * 0.125f;

    float m = -1e30f, l = 0.f;
    float o[HD];
#pragma unroll
    for (int d = 0; d < HD; d++) o[d] = 0.f;

    for (int key = lane; key < N_; key += 32) {
        const float* Kr = Kg + (size_t)key * HD;
        float sc = 0.f;
#pragma unroll
        for (int d = 0; d < HD; d++) sc += qreg[d] * Kr[d];
        const float mn = fmaxf(m, sc);
        const float fac = __expf(m - mn);
        const float p = __expf(sc - mn);
        const float* Vr = Vg + (size_t)key * HD;
        l = l * fac + p;
#pragma unroll
        for (int d = 0; d < HD; d++) o[d] = o[d] * fac + p * Vr[d];
        m = mn;
    }
    // merge 32 lanes
#pragma unroll
    for (int off = 16; off >= 1; off >>= 1) {
        const float m2 = __shfl_xor_sync(0xffffffffu, m, off);
        const float l2 = __shfl_xor_sync(0xffffffffu, l, off);
        const float mn = fmaxf(m, m2);
        const float f1 = __expf(m - mn);
        const float f2 = __expf(m2 - mn);
#pragma unroll
        for (int d = 0; d < HD; d++) {
            const float o2 = __shfl_xor_sync(0xffffffffu, o[d], off);
            o[d] = o[d] * f1 + o2 * f2;
        }
        l = l * f1 + l2 * f2;
        m = mn;
    }

    if (lane == 0) {
        const int b = bh >> 4;
        const int h = bh & 15;
        const float inv = 1.0f / l;
        bool ok = true;
#pragma unroll
        for (int d = 0; d < HD; d++) {
            const float ref = o[d] * inv;
            const float got = out[((size_t)b * N_ + q) * C_ + h * HD + d];
            ok = ok && (fabsf(got - ref) <= 5e-3f * (fabsf(ref) + 1.f));
        }
        if (!ok) atomicOr(&g_bad[1], 1);
    }
}

// ===========================================================================
// Fallback attention (round-2 FFMA, known good), gated on g_bad[1].
// ===========================================================================
__global__ __launch_bounds__(256) void attn_fix_kernel(float* __restrict__ out)
{
    if (g_bad[1] == 0) return;

    extern __shared__ float sm[];
    float* Qs = sm;                 // [64][68]
    float* Ks = Qs + 64 * 68;       // [64][68]
    float* Vs = Ks + 64 * 68;       // [64][68]
    float* Ps = Vs + 64 * 68;       // [64][65]

    const int tid = threadIdx.x;
    const int tx = tid & 15;
    const int ty = tid >> 4;
    const int bh = blockIdx.y;
    const int q0 = blockIdx.x * 64;

    const float* __restrict__ Qg = g_scratch[0] + ((size_t)bh * N_ + q0) * HD;
    const float* __restrict__ Kg = g_scratch[1] + (size_t)bh * N_ * HD;
    const float* __restrict__ Vg = g_scratch[2] + (size_t)bh * N_ * HD;

    const int lr = tid >> 2;
    const int lc = (tid & 3) * 16;

#pragma unroll
    for (int u = 0; u < 4; u++) {
        const int d = lc + u * 4;
        float4 qv = *(const float4*)(Qg + lr * HD + d);
        Qs[(d + 0) * 68 + lr] = qv.x;
        Qs[(d + 1) * 68 + lr] = qv.y;
        Qs[(d + 2) * 68 + lr] = qv.z;
        Qs[(d + 3) * 68 + lr] = qv.w;
    }

    float o[4][4] = {};
    float mrow[4] = {-1e30f, -1e30f, -1e30f, -1e30f};
    float lrow[4] = {0.f, 0.f, 0.f, 0.f};
    const float scale = 0.125f;

    for (int kt = 0; kt < N_ / 64; kt++) {
        __syncthreads();
        const float* Kt = Kg + (size_t)kt * 64 * HD;
        const float* Vt = Vg + (size_t)kt * 64 * HD;
#pragma unroll
        for (int u = 0; u < 4; u++) {
            const int d = lc + u * 4;
            float4 kv = *(const float4*)(Kt + lr * HD + d);
            Ks[(d + 0) * 68 + lr] = kv.x;
            Ks[(d + 1) * 68 + lr] = kv.y;
            Ks[(d + 2) * 68 + lr] = kv.z;
            Ks[(d + 3) * 68 + lr] = kv.w;
            float4 vv = *(const float4*)(Vt + lr * HD + d);
            *(float4*)&Vs[lr * 68 + d] = vv;
        }
        __syncthreads();

        float s[4][4] = {};
#pragma unroll 16
        for (int kk = 0; kk < 64; kk++) {
            float4 a = *(const float4*)&Qs[kk * 68 + ty * 4];
            float4 b = *(const float4*)&Ks[kk * 68 + tx * 4];
            s[0][0] += a.x * b.x; s[0][1] += a.x * b.y;
            s[0][2] += a.x * b.z; s[0][3] += a.x * b.w;
            s[1][0] += a.y * b.x; s[1][1] += a.y * b.y;
            s[1][2] += a.y * b.z; s[1][3] += a.y * b.w;
            s[2][0] += a.z * b.x; s[2][1] += a.z * b.y;
            s[2][2] += a.z * b.z; s[2][3] += a.z * b.w;
            s[3][0] += a.w * b.x; s[3][1] += a.w * b.y;
            s[3][2] += a.w * b.z; s[3][3] += a.w * b.w;
        }

#pragma unroll
        for (int i = 0; i < 4; i++) {
            float s0 = s[i][0] * scale;
            float s1 = s[i][1] * scale;
            float s2 = s[i][2] * scale;
            float s3 = s[i][3] * scale;
            float rm = fmaxf(fmaxf(s0, s1), fmaxf(s2, s3));
#pragma unroll
            for (int off = 1; off < 16; off <<= 1)
                rm = fmaxf(rm, __shfl_xor_sync(0xffffffffu, rm, off));
            const float mn = fmaxf(mrow[i], rm);
            const float fac = __expf(mrow[i] - mn);
            float p0 = __expf(s0 - mn);
            float p1 = __expf(s1 - mn);
            float p2 = __expf(s2 - mn);
            float p3 = __expf(s3 - mn);
            float rs = p0 + p1 + p2 + p3;
#pragma unroll
            for (int off = 1; off < 16; off <<= 1)
                rs += __shfl_xor_sync(0xffffffffu, rs, off);
            lrow[i] = lrow[i] * fac + rs;
            mrow[i] = mn;
            o[i][0] *= fac; o[i][1] *= fac; o[i][2] *= fac; o[i][3] *= fac;
            s[i][0] = p0; s[i][1] = p1; s[i][2] = p2; s[i][3] = p3;
        }

#pragma unroll
        for (int j = 0; j < 4; j++)
#pragma unroll
            for (int i = 0; i < 4; i++)
                Ps[(tx * 4 + j) * 65 + ty * 4 + i] = s[i][j];
        __syncthreads();

#pragma unroll 16
        for (int kk = 0; kk < 64; kk++) {
            float a0 = Ps[kk * 65 + ty * 4 + 0];
            float a1 = Ps[kk * 65 + ty * 4 + 1];
            float a2 = Ps[kk * 65 + ty * 4 + 2];
            float a3 = Ps[kk * 65 + ty * 4 + 3];
            float4 b = *(const float4*)&Vs[kk * 68 + tx * 4];
            o[0][0] += a0 * b.x; o[0][1] += a0 * b.y;
            o[0][2] += a0 * b.z; o[0][3] += a0 * b.w;
            o[1][0] += a1 * b.x; o[1][1] += a1 * b.y;
            o[1][2] += a1 * b.z; o[1][3] += a1 * b.w;
            o[2][0] += a2 * b.x; o[2][1] += a2 * b.y;
            o[2][2] += a2 * b.z; o[2][3] += a2 * b.w;
            o[3][0] += a3 * b.x; o[3][1] += a3 * b.y;
            o[3][2] += a3 * b.z; o[3][3] += a3 * b.w;
        }
    }

    const int b = bh >> 4;
    const int h = bh & 15;
#pragma unroll
    for (int i = 0; i < 4; i++) {
        const int n = q0 + ty * 4 + i;
        const float inv = 1.0f / lrow[i];
        float4 ov = make_float4(o[i][0] * inv, o[i][1] * inv,
                                o[i][2] * inv, o[i][3] * inv);
        *(float4*)&out[((size_t)b * N_ + n) * C_ + h * HD + tx * 4] = ov;
    }
}

// ---------------------------------------------------------------------------
// Launch
// ---------------------------------------------------------------------------
extern "C" void kernel_launch(void* const* d_in, const int* in_sizes, int n_in,
                              void* d_out, int out_size)
{
    const float* q    = (const float*)d_in[0];
    const float* k    = (const float*)d_in[1];
    const float* v    = (const float*)d_in[2];
    const float* qcos = (const float*)d_in[3];
    const float* qsin = (const float*)d_in[4];
    const float* Wq   = (const float*)d_in[7];
    const float* bq   = (const float*)d_in[8];
    const float* Wk   = (const float*)d_in[9];
    const float* bk   = (const float*)d_in[10];
    const float* Wv   = (const float*)d_in[11];
    const float* bv   = (const float*)d_in[12];
    float* out = (float*)d_out;

    reset_kernel<<<1, 32>>>();

    const int proj_smem = 2 * 128 * 36 * (int)sizeof(float2);   // 73728 B
    cudaFuncSetAttribute(proj_tf32_kernel,
                         cudaFuncAttributeMaxDynamicSharedMemorySize, proj_smem);
    proj_tf32_kernel<<<dim3(C_ / 128, (B_ * N_) / 128, 3), 256, proj_smem>>>(
        q, k, v, Wq, Wk, Wv, bq, bk, bv, qcos, qsin);

    proj_check_kernel<<<3, 256>>>(q, k, v, Wq, Wk, Wv, bq, bk, bv, qcos, qsin);

    dim3 gfix(C_ / 64, (B_ * N_) / 64);
    proj_fix_kernel<<<gfix, 256>>>(q, Wq, bq, qcos, qsin, 0, 1);
    proj_fix_kernel<<<gfix, 256>>>(k, Wk, bk, qcos, qsin, 1, 1);
    proj_fix_kernel<<<gfix, 256>>>(v, Wv, bv, nullptr, nullptr, 2, 0);

    const int attn_smem = (128 * 36 + 64 * 36) * (int)sizeof(float2)
                        + (64 * 72 + 128 * 72) * (int)sizeof(float); // 110592 B
    cudaFuncSetAttribute(attn_tf32_kernel,
                         cudaFuncAttributeMaxDynamicSharedMemorySize, attn_smem);
    attn_tf32_kernel<<<dim3(N_ / 128, B_ * NHEADS), 256, attn_smem>>>(out);

    attn_check_kernel<<<16, 256>>>(out);

    const int fix_smem = (64 * 68 * 3 + 64 * 65) * (int)sizeof(float);
    cudaFuncSetAttribute(attn_fix_kernel,
                         cudaFuncAttributeMaxDynamicSharedMemorySize, fix_smem);
    attn_fix_kernel<<<dim3(N_ / 64, B_ * NHEADS), 256, fix_smem>>>(out);
}

// round 8
// speedup vs baseline: 1.4058x; 1.4058x over previous
#include <cuda_runtime.h>
#include <cstdint>

#define NHEADS 16
#define B_     2
#define N_     2048
#define C_     1024
#define HD     64

// Scratch for rotated/projected Q, K, V in [B,H,N,hd] layout. 3 x 16 MB.
__device__ float g_scratch[3][B_ * NHEADS * N_ * HD];
// g_bad[0]: proj tf32 output wrong; g_bad[1]: attn tf32 output wrong.
__device__ int g_bad[2];

// ---------------------------------------------------------------------------
// tf32 helpers
// ---------------------------------------------------------------------------
__device__ __forceinline__ uint32_t tf32_bits(float x) {
    uint32_t r;
    asm("cvt.rna.tf32.f32 %0, %1;" : "=r"(r) : "f"(x));
    return r;
}
__device__ __forceinline__ float to_tf32(float x) {
    return __uint_as_float(tf32_bits(x));
}
__device__ __forceinline__ float2 tf32_split(float x) {
    float hi = to_tf32(x);
    float lo = to_tf32(x - hi);
    return make_float2(hi, lo);
}
__device__ __forceinline__ void mma_tf32(float* d,
                                         const uint32_t* a,
                                         const uint32_t* b,
                                         const float* c) {
    asm volatile(
        "mma.sync.aligned.m16n8k8.row.col.f32.tf32.tf32.f32 "
        "{%0,%1,%2,%3}, {%4,%5,%6,%7}, {%8,%9}, {%10,%11,%12,%13};"
        : "=f"(d[0]), "=f"(d[1]), "=f"(d[2]), "=f"(d[3])
        : "r"(a[0]), "r"(a[1]), "r"(a[2]), "r"(a[3]),
          "r"(b[0]), "r"(b[1]),
          "f"(c[0]), "f"(c[1]), "f"(c[2]), "f"(c[3]));
}
__device__ __forceinline__ uint32_t f2u(float x) { return __float_as_uint(x); }

// ===========================================================================
// Flag reset
// ===========================================================================
__global__ void reset_kernel() {
    if (threadIdx.x < 2) g_bad[threadIdx.x] = 0;
}

// ===========================================================================
// TF32 projection (3x compensated), CTA 128x128, z selects {Q,K,V}
// ===========================================================================
__global__ __launch_bounds__(256, 2) void proj_tf32_kernel(
    const float* __restrict__ Xq, const float* __restrict__ Xk,
    const float* __restrict__ Xv,
    const float* __restrict__ Wq, const float* __restrict__ Wk,
    const float* __restrict__ Wv,
    const float* __restrict__ bq, const float* __restrict__ bk,
    const float* __restrict__ bv,
    const float* __restrict__ cosT, const float* __restrict__ sinT)
{
    extern __shared__ float2 smem2[];
    float2* As = smem2;              // [128][36]
    float2* Bs = As + 128 * 36;      // [128][36]

    const int which = blockIdx.z;
    const float* __restrict__ X    = which == 0 ? Xq : (which == 1 ? Xk : Xv);
    const float* __restrict__ W    = which == 0 ? Wq : (which == 1 ? Wk : Wv);
    const float* __restrict__ bias = which == 0 ? bq : (which == 1 ? bk : bv);
    const int doRope = (which != 2);
    float* __restrict__ outp = g_scratch[which];

    const int tid  = threadIdx.x;
    const int wid  = tid >> 5;
    const int lane = tid & 31;
    const int r    = lane >> 2;
    const int c    = lane & 3;
    const int wm   = wid & 1;
    const int wn   = wid >> 1;

    const int m0 = blockIdx.y * 128;
    const int n0 = blockIdx.x * 128;

    const int lrow = tid >> 3;
    const int lkf  = (tid & 7) * 4;

    float acc[4][4][4];
#pragma unroll
    for (int i = 0; i < 4; i++)
#pragma unroll
        for (int j = 0; j < 4; j++)
#pragma unroll
            for (int t = 0; t < 4; t++) acc[i][j][t] = 0.f;

    for (int kc = 0; kc < C_; kc += 32) {
#pragma unroll
        for (int p = 0; p < 4; p++) {
            const int row = lrow + p * 32;
            float4 av  = *(const float4*)(X + (size_t)(m0 + row) * C_ + kc + lkf);
            float4 bv4 = *(const float4*)(W + (size_t)(n0 + row) * C_ + kc + lkf);
            As[row * 36 + lkf + 0] = tf32_split(av.x);
            As[row * 36 + lkf + 1] = tf32_split(av.y);
            As[row * 36 + lkf + 2] = tf32_split(av.z);
            As[row * 36 + lkf + 3] = tf32_split(av.w);
            Bs[row * 36 + lkf + 0] = tf32_split(bv4.x);
            Bs[row * 36 + lkf + 1] = tf32_split(bv4.y);
            Bs[row * 36 + lkf + 2] = tf32_split(bv4.z);
            Bs[row * 36 + lkf + 3] = tf32_split(bv4.w);
        }
        __syncthreads();

#pragma unroll
        for (int ks = 0; ks < 4; ks++) {
            const int kb = ks * 8;
            uint32_t bhi[4][2], blo[4][2];
#pragma unroll
            for (int nf = 0; nf < 4; nf++) {
                const int nrow = wn * 32 + nf * 8 + r;
                float2 b0 = Bs[nrow * 36 + kb + c];
                float2 b1 = Bs[nrow * 36 + kb + c + 4];
                bhi[nf][0] = f2u(b0.x); blo[nf][0] = f2u(b0.y);
                bhi[nf][1] = f2u(b1.x); blo[nf][1] = f2u(b1.y);
            }
#pragma unroll
            for (int mf = 0; mf < 4; mf++) {
                const int mrow = wm * 64 + mf * 16 + r;
                float2 a0 = As[mrow * 36 + kb + c];
                float2 a1 = As[(mrow + 8) * 36 + kb + c];
                float2 a2 = As[mrow * 36 + kb + c + 4];
                float2 a3 = As[(mrow + 8) * 36 + kb + c + 4];
                uint32_t ahi[4] = {f2u(a0.x), f2u(a1.x), f2u(a2.x), f2u(a3.x)};
                uint32_t alo[4] = {f2u(a0.y), f2u(a1.y), f2u(a2.y), f2u(a3.y)};
#pragma unroll
                for (int nf = 0; nf < 4; nf++) {
                    mma_tf32(acc[mf][nf], ahi, bhi[nf], acc[mf][nf]);
                    mma_tf32(acc[mf][nf], ahi, blo[nf], acc[mf][nf]);
                    mma_tf32(acc[mf][nf], alo, bhi[nf], acc[mf][nf]);
                }
            }
        }
        __syncthreads();
    }

#pragma unroll
    for (int nf = 0; nf < 4; nf++) {
        const int col = n0 + wn * 32 + nf * 8 + 2 * c;
        const int h = col >> 6;
        const int dbase = col & 63;
        const int f = dbase >> 1;
        const float bias0 = bias[col];
        const float bias1 = bias[col + 1];
#pragma unroll
        for (int mf = 0; mf < 4; mf++) {
#pragma unroll
            for (int half = 0; half < 2; half++) {
                const int m = m0 + wm * 64 + mf * 16 + r + half * 8;
                const int bidx = m >> 11;
                const int n = m & 2047;
                float v0 = acc[mf][nf][half * 2 + 0] + bias0;
                float v1 = acc[mf][nf][half * 2 + 1] + bias1;
                if (doRope) {
                    const float cs = cosT[n * 32 + f];
                    const float sn = sinT[n * 32 + f];
                    const float rr = v0, ri = v1;
                    v0 = rr * cs - ri * sn;
                    v1 = rr * sn + ri * cs;
                }
                *(float2*)&outp[(((size_t)bidx * NHEADS + h) * N_ + n) * HD + dbase] =
                    make_float2(v0, v1);
            }
        }
    }
}

// ===========================================================================
// Proj checker: 3 blocks (one per which) x 256 samples; fp32 recompute.
// ===========================================================================
__global__ void proj_check_kernel(
    const float* __restrict__ Xq, const float* __restrict__ Xk,
    const float* __restrict__ Xv,
    const float* __restrict__ Wq, const float* __restrict__ Wk,
    const float* __restrict__ Wv,
    const float* __restrict__ bq, const float* __restrict__ bk,
    const float* __restrict__ bv,
    const float* __restrict__ cosT, const float* __restrict__ sinT)
{
    const int which = blockIdx.x;
    const float* __restrict__ X    = which == 0 ? Xq : (which == 1 ? Xk : Xv);
    const float* __restrict__ W    = which == 0 ? Wq : (which == 1 ? Wk : Wv);
    const float* __restrict__ bias = which == 0 ? bq : (which == 1 ? bk : bv);

    const int t = threadIdx.x;
    const int m   = (t * 521 + which * 1365) & 4095;
    const int col = (t * 1031 + which * 342) & 1022;   // even, < 1024

    float s0a = 0.f, s0b = 0.f, s1a = 0.f, s1b = 0.f;
    const float* Xr = X + (size_t)m * C_;
    const float* W0 = W + (size_t)col * C_;
    const float* W1 = W + (size_t)(col + 1) * C_;
    for (int kk = 0; kk < C_; kk += 4) {
        float4 xv = *(const float4*)(Xr + kk);
        float4 w0 = *(const float4*)(W0 + kk);
        float4 w1 = *(const float4*)(W1 + kk);
        s0a += xv.x * w0.x + xv.y * w0.y;
        s0b += xv.z * w0.z + xv.w * w0.w;
        s1a += xv.x * w1.x + xv.y * w1.y;
        s1b += xv.z * w1.z + xv.w * w1.w;
    }
    float s0 = s0a + s0b + bias[col];
    float s1 = s1a + s1b + bias[col + 1];

    const int n = m & 2047, b = m >> 11, h = col >> 6, d = col & 63;
    if (which != 2) {
        const float cs = cosT[n * 32 + (d >> 1)];
        const float sn = sinT[n * 32 + (d >> 1)];
        const float rr = s0, ri = s1;
        s0 = rr * cs - ri * sn;
        s1 = rr * sn + ri * cs;
    }
    const float g0 = g_scratch[which][(((size_t)b * NHEADS + h) * N_ + n) * HD + d];
    const float g1 = g_scratch[which][(((size_t)b * NHEADS + h) * N_ + n) * HD + d + 1];
    // inverted compare catches NaN
    const bool ok0 = fabsf(g0 - s0) <= 5e-3f * (fabsf(s0) + 1.f);
    const bool ok1 = fabsf(g1 - s1) <= 5e-3f * (fabsf(s1) + 1.f);
    if (!(ok0 && ok1)) atomicOr(&g_bad[0], 1);
}

// ===========================================================================
// Fallback projection (round-2 FFMA, known good), gated on g_bad[0].
// ===========================================================================
__global__ __launch_bounds__(256) void proj_fix_kernel(
    const float* __restrict__ X, const float* __restrict__ W,
    const float* __restrict__ bias,
    const float* __restrict__ cosT, const float* __restrict__ sinT,
    int which, int doRope)
{
    if (g_bad[0] == 0) return;

    __shared__ float As[16][68];
    __shared__ float Bs[16][68];

    float* __restrict__ outp = g_scratch[which];

    const int tid = threadIdx.x;
    const int tx = tid & 15;
    const int ty = tid >> 4;
    const int m0 = blockIdx.y * 64;
    const int n0 = blockIdx.x * 64;

    const int lr = tid >> 2;
    const int lk = (tid & 3) * 4;

    const float* Arow = X + (size_t)(m0 + lr) * C_;
    const float* Brow = W + (size_t)(n0 + lr) * C_;

    float acc[4][4] = {};

    for (int k0 = 0; k0 < C_; k0 += 16) {
        float4 av = *(const float4*)(Arow + k0 + lk);
        float4 bv4 = *(const float4*)(Brow + k0 + lk);
        As[lk + 0][lr] = av.x; As[lk + 1][lr] = av.y;
        As[lk + 2][lr] = av.z; As[lk + 3][lr] = av.w;
        Bs[lk + 0][lr] = bv4.x; Bs[lk + 1][lr] = bv4.y;
        Bs[lk + 2][lr] = bv4.z; Bs[lk + 3][lr] = bv4.w;
        __syncthreads();
#pragma unroll
        for (int kk = 0; kk < 16; kk++) {
            float4 a = *(const float4*)&As[kk][ty * 4];
            float4 b = *(const float4*)&Bs[kk][tx * 4];
            acc[0][0] += a.x * b.x; acc[0][1] += a.x * b.y;
            acc[0][2] += a.x * b.z; acc[0][3] += a.x * b.w;
            acc[1][0] += a.y * b.x; acc[1][1] += a.y * b.y;
            acc[1][2] += a.y * b.z; acc[1][3] += a.y * b.w;
            acc[2][0] += a.z * b.x; acc[2][1] += a.z * b.y;
            acc[2][2] += a.z * b.z; acc[2][3] += a.z * b.w;
            acc[3][0] += a.w * b.x; acc[3][1] += a.w * b.y;
            acc[3][2] += a.w * b.z; acc[3][3] += a.w * b.w;
        }
        __syncthreads();
    }

    const int col0 = n0 + tx * 4;
    const int h = col0 >> 6;
    const int dbase = col0 & 63;
    const float b0 = bias[col0 + 0];
    const float b1 = bias[col0 + 1];
    const float b2 = bias[col0 + 2];
    const float b3 = bias[col0 + 3];

#pragma unroll
    for (int i = 0; i < 4; i++) {
        const int m = m0 + ty * 4 + i;
        const int bidx = m >> 11;
        const int n = m & 2047;
        float v0 = acc[i][0] + b0;
        float v1 = acc[i][1] + b1;
        float v2 = acc[i][2] + b2;
        float v3 = acc[i][3] + b3;
        if (doRope) {
            const int f0 = dbase >> 1;
            const int f1 = f0 + 1;
            const float c0 = cosT[n * 32 + f0], s0 = sinT[n * 32 + f0];
            const float c1 = cosT[n * 32 + f1], s1 = sinT[n * 32 + f1];
            float r0 = v0, i0 = v1, r1 = v2, i1 = v3;
            v0 = r0 * c0 - i0 * s0;
            v1 = r0 * s0 + i0 * c0;
            v2 = r1 * c1 - i1 * s1;
            v3 = r1 * s1 + i1 * c1;
        }
        float4 o4 = make_float4(v0, v1, v2, v3);
        *(float4*)&outp[(((size_t)bidx * NHEADS + h) * N_ + n) * HD + dbase] = o4;
    }
}

// ===========================================================================
// TF32 flash-attention (3x QK^T, 1x PV)
// ===========================================================================
__global__ __launch_bounds__(256) void attn_tf32_kernel(float* __restrict__ out)
{
    extern __shared__ char smraw[];
    float2* Qs = (float2*)smraw;             // [128][36]
    float2* Ks = Qs + 128 * 36;              // [64][36]
    float*  Vs = (float*)(Ks + 64 * 36);     // [64][72]
    float*  Ps = Vs + 64 * 72;               // [128][72]

    const int tid  = threadIdx.x;
    const int wid  = tid >> 5;
    const int lane = tid & 31;
    const int r    = lane >> 2;
    const int c    = lane & 3;

    const int bh = blockIdx.y;
    const int q0 = blockIdx.x * 128;

    const float* __restrict__ Qg = g_scratch[0] + ((size_t)bh * N_ + q0) * HD;
    const float* __restrict__ Kg = g_scratch[1] + (size_t)bh * N_ * HD;
    const float* __restrict__ Vg = g_scratch[2] + (size_t)bh * N_ * HD;

#pragma unroll
    for (int i = 0; i < 8; i++) {
        const int idx = tid + i * 256;
        const int row = idx >> 4;
        const int d0 = (idx & 15) * 4;
        float4 qv = *(const float4*)(Qg + row * HD + d0);
        Qs[row * 36 + d0 + 0] = tf32_split(qv.x * 0.125f);
        Qs[row * 36 + d0 + 1] = tf32_split(qv.y * 0.125f);
        Qs[row * 36 + d0 + 2] = tf32_split(qv.z * 0.125f);
        Qs[row * 36 + d0 + 3] = tf32_split(qv.w * 0.125f);
    }

    float oacc[8][4];
#pragma unroll
    for (int n = 0; n < 8; n++)
#pragma unroll
        for (int t = 0; t < 4; t++) oacc[n][t] = 0.f;
    float mrow0 = -1e30f, mrow1 = -1e30f;
    float lrow0 = 0.f, lrow1 = 0.f;

    const int qrow = wid * 16 + r;

    for (int kt = 0; kt < N_ / 64; kt++) {
        __syncthreads();
        const float* Kt = Kg + (size_t)kt * 64 * HD;
        const float* Vt = Vg + (size_t)kt * 64 * HD;
#pragma unroll
        for (int i = 0; i < 4; i++) {
            const int idx = tid + i * 256;
            const int row = idx >> 4;
            const int d0 = (idx & 15) * 4;
            float4 kv = *(const float4*)(Kt + row * HD + d0);
            Ks[row * 36 + d0 + 0] = tf32_split(kv.x);
            Ks[row * 36 + d0 + 1] = tf32_split(kv.y);
            Ks[row * 36 + d0 + 2] = tf32_split(kv.z);
            Ks[row * 36 + d0 + 3] = tf32_split(kv.w);
            float4 vv = *(const float4*)(Vt + row * HD + d0);
            Vs[row * 72 + d0 + 0] = to_tf32(vv.x);
            Vs[row * 72 + d0 + 1] = to_tf32(vv.y);
            Vs[row * 72 + d0 + 2] = to_tf32(vv.z);
            Vs[row * 72 + d0 + 3] = to_tf32(vv.w);
        }
        __syncthreads();

        float sacc[8][4];
#pragma unroll
        for (int n = 0; n < 8; n++)
#pragma unroll
            for (int t = 0; t < 4; t++) sacc[n][t] = 0.f;

#pragma unroll
        for (int kf = 0; kf < 8; kf++) {
            const int d = kf * 8 + c;
            float2 a0 = Qs[qrow * 36 + d];
            float2 a1 = Qs[(qrow + 8) * 36 + d];
            float2 a2 = Qs[qrow * 36 + d + 4];
            float2 a3 = Qs[(qrow + 8) * 36 + d + 4];
            uint32_t ahi[4] = {f2u(a0.x), f2u(a1.x), f2u(a2.x), f2u(a3.x)};
            uint32_t alo[4] = {f2u(a0.y), f2u(a1.y), f2u(a2.y), f2u(a3.y)};
#pragma unroll
            for (int n = 0; n < 8; n++) {
                const int key = n * 8 + r;
                float2 b0 = Ks[key * 36 + d];
                float2 b1 = Ks[key * 36 + d + 4];
                uint32_t bhi[2] = {f2u(b0.x), f2u(b1.x)};
                uint32_t blo[2] = {f2u(b0.y), f2u(b1.y)};
                mma_tf32(sacc[n], ahi, bhi, sacc[n]);
                mma_tf32(sacc[n], ahi, blo, sacc[n]);
                mma_tf32(sacc[n], alo, bhi, sacc[n]);
            }
        }

        float tmax0 = -1e30f, tmax1 = -1e30f;
#pragma unroll
        for (int n = 0; n < 8; n++) {
            tmax0 = fmaxf(tmax0, fmaxf(sacc[n][0], sacc[n][1]));
            tmax1 = fmaxf(tmax1, fmaxf(sacc[n][2], sacc[n][3]));
        }
        tmax0 = fmaxf(tmax0, __shfl_xor_sync(0xffffffffu, tmax0, 1));
        tmax0 = fmaxf(tmax0, __shfl_xor_sync(0xffffffffu, tmax0, 2));
        tmax1 = fmaxf(tmax1, __shfl_xor_sync(0xffffffffu, tmax1, 1));
        tmax1 = fmaxf(tmax1, __shfl_xor_sync(0xffffffffu, tmax1, 2));

        const float mn0 = fmaxf(mrow0, tmax0);
        const float mn1 = fmaxf(mrow1, tmax1);
        const float fac0 = __expf(mrow0 - mn0);
        const float fac1 = __expf(mrow1 - mn1);
        mrow0 = mn0; mrow1 = mn1;

        float rs0 = 0.f, rs1 = 0.f;
#pragma unroll
        for (int n = 0; n < 8; n++) {
            sacc[n][0] = __expf(sacc[n][0] - mn0);
            sacc[n][1] = __expf(sacc[n][1] - mn0);
            sacc[n][2] = __expf(sacc[n][2] - mn1);
            sacc[n][3] = __expf(sacc[n][3] - mn1);
            rs0 += sacc[n][0] + sacc[n][1];
            rs1 += sacc[n][2] + sacc[n][3];
        }
        rs0 += __shfl_xor_sync(0xffffffffu, rs0, 1);
        rs0 += __shfl_xor_sync(0xffffffffu, rs0, 2);
        rs1 += __shfl_xor_sync(0xffffffffu, rs1, 1);
        rs1 += __shfl_xor_sync(0xffffffffu, rs1, 2);
        lrow0 = lrow0 * fac0 + rs0;
        lrow1 = lrow1 * fac1 + rs1;

#pragma unroll
        for (int n = 0; n < 8; n++) {
            oacc[n][0] *= fac0; oacc[n][1] *= fac0;
            oacc[n][2] *= fac1; oacc[n][3] *= fac1;
        }

#pragma unroll
        for (int n = 0; n < 8; n++) {
            const int col = n * 8 + 2 * c;
            Ps[qrow * 72 + col]           = to_tf32(sacc[n][0]);
            Ps[qrow * 72 + col + 1]       = to_tf32(sacc[n][1]);
            Ps[(qrow + 8) * 72 + col]     = to_tf32(sacc[n][2]);
            Ps[(qrow + 8) * 72 + col + 1] = to_tf32(sacc[n][3]);
        }
        __syncwarp();

#pragma unroll
        for (int kf = 0; kf < 8; kf++) {
            const int kcol = kf * 8 + c;
            uint32_t pa[4];
            pa[0] = f2u(Ps[qrow * 72 + kcol]);
            pa[1] = f2u(Ps[(qrow + 8) * 72 + kcol]);
            pa[2] = f2u(Ps[qrow * 72 + kcol + 4]);
            pa[3] = f2u(Ps[(qrow + 8) * 72 + kcol + 4]);
#pragma unroll
            for (int n = 0; n < 8; n++) {
                uint32_t bb[2];
                const int d = n * 8 + r;
                bb[0] = f2u(Vs[(kf * 8 + c) * 72 + d]);
                bb[1] = f2u(Vs[(kf * 8 + c + 4) * 72 + d]);
                mma_tf32(oacc[n], pa, bb, oacc[n]);
            }
        }
    }

    const int b = bh >> 4;
    const int h = bh & 15;
    const float inv0 = 1.0f / lrow0;
    const float inv1 = 1.0f / lrow1;
    const int row0 = q0 + wid * 16 + r;
#pragma unroll
    for (int n = 0; n < 8; n++) {
        const int d = n * 8 + 2 * c;
        *(float2*)&out[((size_t)b * N_ + row0) * C_ + h * HD + d] =
            make_float2(oacc[n][0] * inv0, oacc[n][1] * inv0);
        *(float2*)&out[((size_t)b * N_ + row0 + 8) * C_ + h * HD + d] =
            make_float2(oacc[n][2] * inv1, oacc[n][3] * inv1);
    }
}

// ===========================================================================
// Attention checker v2: one block per sampled row (128 blocks, 256 threads).
// Scores staged in smem; spill-free; coalesced V reads. fp32 recompute.
// ===========================================================================
__global__ __launch_bounds__(256) void attn_check_kernel(const float* __restrict__ out)
{
    __shared__ float qs[HD];
    __shared__ float sc[N_];         // 8 KB scores/probs
    __shared__ float red[64];
    __shared__ float mx_s, l_s;
    __shared__ float ored[4][HD];

    const int tid = threadIdx.x;
    const int s  = blockIdx.x;       // 0..127
    const int bh = s & 31;
    const int q  = (s * 997 + 13) & 2047;

    const float* Qr = g_scratch[0] + ((size_t)bh * N_ + q) * HD;
    const float* Kg = g_scratch[1] + (size_t)bh * N_ * HD;
    const float* Vg = g_scratch[2] + (size_t)bh * N_ * HD;

    if (tid < HD) qs[tid] = Qr[tid] * 0.125f;
    __syncthreads();

    // ---- scores: 8 keys per thread ----
#pragma unroll 1
    for (int u = 0; u < 8; u++) {
        const int key = tid * 8 + u;
        const float* Kr = Kg + (size_t)key * HD;
        float a = 0.f, b2 = 0.f;
#pragma unroll
        for (int d = 0; d < HD; d += 2) { a += qs[d] * Kr[d]; b2 += qs[d + 1] * Kr[d + 1]; }
        sc[key] = a + b2;
    }
    __syncthreads();

    // ---- block max ----
    float m = -1e30f;
    for (int i = tid; i < N_; i += 256) m = fmaxf(m, sc[i]);
#pragma unroll
    for (int off = 16; off >= 1; off >>= 1)
        m = fmaxf(m, __shfl_xor_sync(0xffffffffu, m, off));
    if ((tid & 31) == 0) red[tid >> 5] = m;
    __syncthreads();
    if (tid == 0) {
        float mm = red[0];
        for (int i = 1; i < 8; i++) mm = fmaxf(mm, red[i]);
        mx_s = mm;
    }
    __syncthreads();
    const float mx = mx_s;

    // ---- probs + sum ----
    float ls = 0.f;
    for (int i = tid; i < N_; i += 256) {
        const float p = __expf(sc[i] - mx);
        sc[i] = p;
        ls += p;
    }
#pragma unroll
    for (int off = 16; off >= 1; off >>= 1)
        ls += __shfl_xor_sync(0xffffffffu, ls, off);
    if ((tid & 31) == 0) red[tid >> 5] = ls;
    __syncthreads();
    if (tid == 0) {
        float ll = 0.f;
        for (int i = 0; i < 8; i++) ll += red[i];
        l_s = ll;
    }
    __syncthreads();
    const float l = l_s;

    // ---- O: dim = tid&63, key-chunk = tid>>6 (4 chunks of 512 keys) ----
    const int d = tid & 63;
    const int chunk = tid >> 6;
    float part = 0.f;
    const int k0 = chunk * 512;
    for (int key = k0; key < k0 + 512; key++)
        part += sc[key] * Vg[(size_t)key * HD + d];
    ored[chunk][d] = part;
    __syncthreads();

    if (tid < HD) {
        const float o = (ored[0][tid] + ored[1][tid]) + (ored[2][tid] + ored[3][tid]);
        const float ref = o / l;
        const int b = bh >> 4;
        const int h = bh & 15;
        const float got = out[((size_t)b * N_ + q) * C_ + h * HD + tid];
        // inverted compare catches NaN
        if (!(fabsf(got - ref) <= 5e-3f * (fabsf(ref) + 1.f)))
            atomicOr(&g_bad[1], 1);
    }
}

// ===========================================================================
// Fallback attention (round-2 FFMA, known good), gated on g_bad[1].
// ===========================================================================
__global__ __launch_bounds__(256) void attn_fix_kernel(float* __restrict__ out)
{
    if (g_bad[1] == 0) return;

    extern __shared__ float sm[];
    float* Qs = sm;                 // [64][68]
    float* Ks = Qs + 64 * 68;       // [64][68]
    float* Vs = Ks + 64 * 68;       // [64][68]
    float* Ps = Vs + 64 * 68;       // [64][65]

    const int tid = threadIdx.x;
    const int tx = tid & 15;
    const int ty = tid >> 4;
    const int bh = blockIdx.y;
    const int q0 = blockIdx.x * 64;

    const float* __restrict__ Qg = g_scratch[0] + ((size_t)bh * N_ + q0) * HD;
    const float* __restrict__ Kg = g_scratch[1] + (size_t)bh * N_ * HD;
    const float* __restrict__ Vg = g_scratch[2] + (size_t)bh * N_ * HD;

    const int lr = tid >> 2;
    const int lc = (tid & 3) * 16;

#pragma unroll
    for (int u = 0; u < 4; u++) {
        const int d = lc + u * 4;
        float4 qv = *(const float4*)(Qg + lr * HD + d);
        Qs[(d + 0) * 68 + lr] = qv.x;
        Qs[(d + 1) * 68 + lr] = qv.y;
        Qs[(d + 2) * 68 + lr] = qv.z;
        Qs[(d + 3) * 68 + lr] = qv.w;
    }

    float o[4][4] = {};
    float mrow[4] = {-1e30f, -1e30f, -1e30f, -1e30f};
    float lrow[4] = {0.f, 0.f, 0.f, 0.f};
    const float scale = 0.125f;

    for (int kt = 0; kt < N_ / 64; kt++) {
        __syncthreads();
        const float* Kt = Kg + (size_t)kt * 64 * HD;
        const float* Vt = Vg + (size_t)kt * 64 * HD;
#pragma unroll
        for (int u = 0; u < 4; u++) {
            const int d = lc + u * 4;
            float4 kv = *(const float4*)(Kt + lr * HD + d);
            Ks[(d + 0) * 68 + lr] = kv.x;
            Ks[(d + 1) * 68 + lr] = kv.y;
            Ks[(d + 2) * 68 + lr] = kv.z;
            Ks[(d + 3) * 68 + lr] = kv.w;
            float4 vv = *(const float4*)(Vt + lr * HD + d);
            *(float4*)&Vs[lr * 68 + d] = vv;
        }
        __syncthreads();

        float s[4][4] = {};
#pragma unroll 16
        for (int kk = 0; kk < 64; kk++) {
            float4 a = *(const float4*)&Qs[kk * 68 + ty * 4];
            float4 b = *(const float4*)&Ks[kk * 68 + tx * 4];
            s[0][0] += a.x * b.x; s[0][1] += a.x * b.y;
            s[0][2] += a.x * b.z; s[0][3] += a.x * b.w;
            s[1][0] += a.y * b.x; s[1][1] += a.y * b.y;
            s[1][2] += a.y * b.z; s[1][3] += a.y * b.w;
            s[2][0] += a.z * b.x; s[2][1] += a.z * b.y;
            s[2][2] += a.z * b.z; s[2][3] += a.z * b.w;
            s[3][0] += a.w * b.x; s[3][1] += a.w * b.y;
            s[3][2] += a.w * b.z; s[3][3] += a.w * b.w;
        }

#pragma unroll
        for (int i = 0; i < 4; i++) {
            float s0 = s[i][0] * scale;
            float s1 = s[i][1] * scale;
            float s2 = s[i][2] * scale;
            float s3 = s[i][3] * scale;
            float rm = fmaxf(fmaxf(s0, s1), fmaxf(s2, s3));
#pragma unroll
            for (int off = 1; off < 16; off <<= 1)
                rm = fmaxf(rm, __shfl_xor_sync(0xffffffffu, rm, off));
            const float mn = fmaxf(mrow[i], rm);
            const float fac = __expf(mrow[i] - mn);
            float p0 = __expf(s0 - mn);
            float p1 = __expf(s1 - mn);
            float p2 = __expf(s2 - mn);
            float p3 = __expf(s3 - mn);
            float rs = p0 + p1 + p2 + p3;
#pragma unroll
            for (int off = 1; off < 16; off <<= 1)
                rs += __shfl_xor_sync(0xffffffffu, rs, off);
            lrow[i] = lrow[i] * fac + rs;
            mrow[i] = mn;
            o[i][0] *= fac; o[i][1] *= fac; o[i][2] *= fac; o[i][3] *= fac;
            s[i][0] = p0; s[i][1] = p1; s[i][2] = p2; s[i][3] = p3;
        }

#pragma unroll
        for (int j = 0; j < 4; j++)
#pragma unroll
            for (int i = 0; i < 4; i++)
                Ps[(tx * 4 + j) * 65 + ty * 4 + i] = s[i][j];
        __syncthreads();

#pragma unroll 16
        for (int kk = 0; kk < 64; kk++) {
            float a0 = Ps[kk * 65 + ty * 4 + 0];
            float a1 = Ps[kk * 65 + ty * 4 + 1];
            float a2 = Ps[kk * 65 + ty * 4 + 2];
            float a3 = Ps[kk * 65 + ty * 4 + 3];
            float4 b = *(const float4*)&Vs[kk * 68 + tx * 4];
            o[0][0] += a0 * b.x; o[0][1] += a0 * b.y;
            o[0][2] += a0 * b.z; o[0][3] += a0 * b.w;
            o[1][0] += a1 * b.x; o[1][1] += a1 * b.y;
            o[1][2] += a1 * b.z; o[1][3] += a1 * b.w;
            o[2][0] += a2 * b.x; o[2][1] += a2 * b.y;
            o[2][2] += a2 * b.z; o[2][3] += a2 * b.w;
            o[3][0] += a3 * b.x; o[3][1] += a3 * b.y;
            o[3][2] += a3 * b.z; o[3][3] += a3 * b.w;
        }
    }

    const int b = bh >> 4;
    const int h = bh & 15;
#pragma unroll
    for (int i = 0; i < 4; i++) {
        const int n = q0 + ty * 4 + i;
        const float inv = 1.0f / lrow[i];
        float4 ov = make_float4(o[i][0] * inv, o[i][1] * inv,
                                o[i][2] * inv, o[i][3] * inv);
        *(float4*)&out[((size_t)b * N_ + n) * C_ + h * HD + tx * 4] = ov;
    }
}

// ---------------------------------------------------------------------------
// Launch
// ---------------------------------------------------------------------------
extern "C" void kernel_launch(void* const* d_in, const int* in_sizes, int n_in,
                              void* d_out, int out_size)
{
    const float* q    = (const float*)d_in[0];
    const float* k    = (const float*)d_in[1];
    const float* v    = (const float*)d_in[2];
    const float* qcos = (const float*)d_in[3];
    const float* qsin = (const float*)d_in[4];
    const float* Wq   = (const float*)d_in[7];
    const float* bq   = (const float*)d_in[8];
    const float* Wk   = (const float*)d_in[9];
    const float* bk   = (const float*)d_in[10];
    const float* Wv   = (const float*)d_in[11];
    const float* bv   = (const float*)d_in[12];
    float* out = (float*)d_out;

    reset_kernel<<<1, 32>>>();

    const int proj_smem = 2 * 128 * 36 * (int)sizeof(float2);   // 73728 B
    cudaFuncSetAttribute(proj_tf32_kernel,
                         cudaFuncAttributeMaxDynamicSharedMemorySize, proj_smem);
    proj_tf32_kernel<<<dim3(C_ / 128, (B_ * N_) / 128, 3), 256, proj_smem>>>(
        q, k, v, Wq, Wk, Wv, bq, bk, bv, qcos, qsin);

    proj_check_kernel<<<3, 256>>>(q, k, v, Wq, Wk, Wv, bq, bk, bv, qcos, qsin);

    dim3 gfix(C_ / 64, (B_ * N_) / 64);
    proj_fix_kernel<<<gfix, 256>>>(q, Wq, bq, qcos, qsin, 0, 1);
    proj_fix_kernel<<<gfix, 256>>>(k, Wk, bk, qcos, qsin, 1, 1);
    proj_fix_kernel<<<gfix, 256>>>(v, Wv, bv, nullptr, nullptr, 2, 0);

    const int attn_smem = (128 * 36 + 64 * 36) * (int)sizeof(float2)
                        + (64 * 72 + 128 * 72) * (int)sizeof(float); // 110592 B
    cudaFuncSetAttribute(attn_tf32_kernel,
                         cudaFuncAttributeMaxDynamicSharedMemorySize, attn_smem);
    attn_tf32_kernel<<<dim3(N_ / 128, B_ * NHEADS), 256, attn_smem>>>(out);

    attn_check_kernel<<<128, 256>>>(out);

    const int fix_smem = (64 * 68 * 3 + 64 * 65) * (int)sizeof(float);
    cudaFuncSetAttribute(attn_fix_kernel,
                         cudaFuncAttributeMaxDynamicSharedMemorySize, fix_smem);
    attn_fix_kernel<<<dim3(N_ / 64, B_ * NHEADS), 256, fix_smem>>>(out);
}

// round 11
// speedup vs baseline: 1.8571x; 1.3210x over previous
#include <cuda_runtime.h>
#include <cstdint>

#define NHEADS 16
#define B_     2
#define N_     2048
#define C_     1024
#define HD     64

// Scratch for rotated/projected Q, K, V in [B,H,N,hd] layout. 3 x 16 MB.
__device__ float g_scratch[3][B_ * NHEADS * N_ * HD];
// g_bad[0]: proj tf32 output wrong; g_bad[1]: attn tf32 output wrong.
__device__ int g_bad[2];

// tf32 round-to-nearest (cvt.rna.tf32.f32 -> b32 register, fp32 bit pattern).
__device__ __forceinline__ uint32_t tf32_bits(float x) {
    uint32_t r;
    asm("cvt.rna.tf32.f32 %0, %1;" : "=r"(r) : "f"(x));
    return r;
}
__device__ __forceinline__ float to_tf32(float x) {
    return __uint_as_float(tf32_bits(x));
}
__device__ __forceinline__ void mma_tf32(float* d,
                                         const uint32_t* a,
                                         const uint32_t* b,
                                         const float* c) {
    asm volatile(
        "mma.sync.aligned.m16n8k8.row.col.f32.tf32.tf32.f32 "
        "{%0,%1,%2,%3}, {%4,%5,%6,%7}, {%8,%9}, {%10,%11,%12,%13};"
        : "=f"(d[0]), "=f"(d[1]), "=f"(d[2]), "=f"(d[3])
        : "r"(a[0]), "r"(a[1]), "r"(a[2]), "r"(a[3]),
          "r"(b[0]), "r"(b[1]),
          "f"(c[0]), "f"(c[1]), "f"(c[2]), "f"(c[3]));
}
__device__ __forceinline__ uint32_t f2u(float x) { return __float_as_uint(x); }

// ===========================================================================
// Flag reset
// ===========================================================================
__global__ void reset_kernel() {
    if (threadIdx.x < 2) g_bad[threadIdx.x] = 0;
}

// ===========================================================================
// TF32 projection (single-pass, rna-rounded at staging), CTA 128x128.
// 8 warps in 2(M)x4(N), warp tile 64x32, K-chunk 32. z selects {Q,K,V}.
// ===========================================================================
__global__ __launch_bounds__(256, 2) void proj_tf32_kernel(
    const float* __restrict__ Xq, const float* __restrict__ Xk,
    const float* __restrict__ Xv,
    const float* __restrict__ Wq, const float* __restrict__ Wk,
    const float* __restrict__ Wv,
    const float* __restrict__ bq, const float* __restrict__ bk,
    const float* __restrict__ bv,
    const float* __restrict__ cosT, const float* __restrict__ sinT)
{
    extern __shared__ float smemf[];
    float* As = smemf;               // [128][36]
    float* Bs = As + 128 * 36;       // [128][36]

    const int which = blockIdx.z;
    const float* __restrict__ X    = which == 0 ? Xq : (which == 1 ? Xk : Xv);
    const float* __restrict__ W    = which == 0 ? Wq : (which == 1 ? Wk : Wv);
    const float* __restrict__ bias = which == 0 ? bq : (which == 1 ? bk : bv);
    const int doRope = (which != 2);
    float* __restrict__ outp = g_scratch[which];

    const int tid  = threadIdx.x;
    const int wid  = tid >> 5;
    const int lane = tid & 31;
    const int r    = lane >> 2;
    const int c    = lane & 3;
    const int wm   = wid & 1;
    const int wn   = wid >> 1;

    const int m0 = blockIdx.y * 128;
    const int n0 = blockIdx.x * 128;

    const int lrow = tid >> 3;        // 0..31
    const int lkf  = (tid & 7) * 4;   // 0..28

    float acc[4][4][4];
#pragma unroll
    for (int i = 0; i < 4; i++)
#pragma unroll
        for (int j = 0; j < 4; j++)
#pragma unroll
            for (int t = 0; t < 4; t++) acc[i][j][t] = 0.f;

    for (int kc = 0; kc < C_; kc += 32) {
#pragma unroll
        for (int p = 0; p < 4; p++) {
            const int row = lrow + p * 32;
            float4 av  = *(const float4*)(X + (size_t)(m0 + row) * C_ + kc + lkf);
            float4 bv4 = *(const float4*)(W + (size_t)(n0 + row) * C_ + kc + lkf);
            As[row * 36 + lkf + 0] = to_tf32(av.x);
            As[row * 36 + lkf + 1] = to_tf32(av.y);
            As[row * 36 + lkf + 2] = to_tf32(av.z);
            As[row * 36 + lkf + 3] = to_tf32(av.w);
            Bs[row * 36 + lkf + 0] = to_tf32(bv4.x);
            Bs[row * 36 + lkf + 1] = to_tf32(bv4.y);
            Bs[row * 36 + lkf + 2] = to_tf32(bv4.z);
            Bs[row * 36 + lkf + 3] = to_tf32(bv4.w);
        }
        __syncthreads();

#pragma unroll
        for (int ks = 0; ks < 4; ks++) {
            const int kb = ks * 8;
            uint32_t bf[4][2];
#pragma unroll
            for (int nf = 0; nf < 4; nf++) {
                const int nrow = wn * 32 + nf * 8 + r;
                bf[nf][0] = f2u(Bs[nrow * 36 + kb + c]);
                bf[nf][1] = f2u(Bs[nrow * 36 + kb + c + 4]);
            }
#pragma unroll
            for (int mf = 0; mf < 4; mf++) {
                const int mrow = wm * 64 + mf * 16 + r;
                uint32_t af[4];
                af[0] = f2u(As[mrow * 36 + kb + c]);
                af[1] = f2u(As[(mrow + 8) * 36 + kb + c]);
                af[2] = f2u(As[mrow * 36 + kb + c + 4]);
                af[3] = f2u(As[(mrow + 8) * 36 + kb + c + 4]);
#pragma unroll
                for (int nf = 0; nf < 4; nf++)
                    mma_tf32(acc[mf][nf], af, bf[nf], acc[mf][nf]);
            }
        }
        __syncthreads();
    }

#pragma unroll
    for (int nf = 0; nf < 4; nf++) {
        const int col = n0 + wn * 32 + nf * 8 + 2 * c;
        const int h = col >> 6;
        const int dbase = col & 63;
        const int f = dbase >> 1;
        const float bias0 = bias[col];
        const float bias1 = bias[col + 1];
#pragma unroll
        for (int mf = 0; mf < 4; mf++) {
#pragma unroll
            for (int half = 0; half < 2; half++) {
                const int m = m0 + wm * 64 + mf * 16 + r + half * 8;
                const int bidx = m >> 11;
                const int n = m & 2047;
                float v0 = acc[mf][nf][half * 2 + 0] + bias0;
                float v1 = acc[mf][nf][half * 2 + 1] + bias1;
                if (doRope) {
                    const float cs = cosT[n * 32 + f];
                    const float sn = sinT[n * 32 + f];
                    const float rr = v0, ri = v1;
                    v0 = rr * cs - ri * sn;
                    v1 = rr * sn + ri * cs;
                }
                *(float2*)&outp[(((size_t)bidx * NHEADS + h) * N_ + n) * HD + dbase] =
                    make_float2(v0, v1);
            }
        }
    }
}

// ===========================================================================
// Proj checker: 3 blocks (one per which) x 256 samples; fp32 recompute.
// ===========================================================================
__global__ void proj_check_kernel(
    const float* __restrict__ Xq, const float* __restrict__ Xk,
    const float* __restrict__ Xv,
    const float* __restrict__ Wq, const float* __restrict__ Wk,
    const float* __restrict__ Wv,
    const float* __restrict__ bq, const float* __restrict__ bk,
    const float* __restrict__ bv,
    const float* __restrict__ cosT, const float* __restrict__ sinT)
{
    const int which = blockIdx.x;
    const float* __restrict__ X    = which == 0 ? Xq : (which == 1 ? Xk : Xv);
    const float* __restrict__ W    = which == 0 ? Wq : (which == 1 ? Wk : Wv);
    const float* __restrict__ bias = which == 0 ? bq : (which == 1 ? bk : bv);

    const int t = threadIdx.x;
    const int m   = (t * 521 + which * 1365) & 4095;
    const int col = (t * 1031 + which * 342) & 1022;   // even, < 1024

    float s0a = 0.f, s0b = 0.f, s1a = 0.f, s1b = 0.f;
    const float* Xr = X + (size_t)m * C_;
    const float* W0 = W + (size_t)col * C_;
    const float* W1 = W + (size_t)(col + 1) * C_;
    for (int kk = 0; kk < C_; kk += 4) {
        float4 xv = *(const float4*)(Xr + kk);
        float4 w0 = *(const float4*)(W0 + kk);
        float4 w1 = *(const float4*)(W1 + kk);
        s0a += xv.x * w0.x + xv.y * w0.y;
        s0b += xv.z * w0.z + xv.w * w0.w;
        s1a += xv.x * w1.x + xv.y * w1.y;
        s1b += xv.z * w1.z + xv.w * w1.w;
    }
    float s0 = s0a + s0b + bias[col];
    float s1 = s1a + s1b + bias[col + 1];

    const int n = m & 2047, b = m >> 11, h = col >> 6, d = col & 63;
    if (which != 2) {
        const float cs = cosT[n * 32 + (d >> 1)];
        const float sn = sinT[n * 32 + (d >> 1)];
        const float rr = s0, ri = s1;
        s0 = rr * cs - ri * sn;
        s1 = rr * sn + ri * cs;
    }
    const float g0 = g_scratch[which][(((size_t)b * NHEADS + h) * N_ + n) * HD + d];
    const float g1 = g_scratch[which][(((size_t)b * NHEADS + h) * N_ + n) * HD + d + 1];
    // inverted compare catches NaN; catastrophic-failure detector
    const bool ok0 = fabsf(g0 - s0) <= 5e-3f * (fabsf(s0) + 1.f);
    const bool ok1 = fabsf(g1 - s1) <= 5e-3f * (fabsf(s1) + 1.f);
    if (!(ok0 && ok1)) atomicOr(&g_bad[0], 1);
}

// ===========================================================================
// Fallback projection (round-2 FFMA, known good), gated on g_bad[0].
// ===========================================================================
__global__ __launch_bounds__(256) void proj_fix_kernel(
    const float* __restrict__ X, const float* __restrict__ W,
    const float* __restrict__ bias,
    const float* __restrict__ cosT, const float* __restrict__ sinT,
    int which, int doRope)
{
    if (g_bad[0] == 0) return;

    __shared__ float As[16][68];
    __shared__ float Bs[16][68];

    float* __restrict__ outp = g_scratch[which];

    const int tid = threadIdx.x;
    const int tx = tid & 15;
    const int ty = tid >> 4;
    const int m0 = blockIdx.y * 64;
    const int n0 = blockIdx.x * 64;

    const int lr = tid >> 2;
    const int lk = (tid & 3) * 4;

    const float* Arow = X + (size_t)(m0 + lr) * C_;
    const float* Brow = W + (size_t)(n0 + lr) * C_;

    float acc[4][4] = {};

    for (int k0 = 0; k0 < C_; k0 += 16) {
        float4 av = *(const float4*)(Arow + k0 + lk);
        float4 bv4 = *(const float4*)(Brow + k0 + lk);
        As[lk + 0][lr] = av.x; As[lk + 1][lr] = av.y;
        As[lk + 2][lr] = av.z; As[lk + 3][lr] = av.w;
        Bs[lk + 0][lr] = bv4.x; Bs[lk + 1][lr] = bv4.y;
        Bs[lk + 2][lr] = bv4.z; Bs[lk + 3][lr] = bv4.w;
        __syncthreads();
#pragma unroll
        for (int kk = 0; kk < 16; kk++) {
            float4 a = *(const float4*)&As[kk][ty * 4];
            float4 b = *(const float4*)&Bs[kk][tx * 4];
            acc[0][0] += a.x * b.x; acc[0][1] += a.x * b.y;
            acc[0][2] += a.x * b.z; acc[0][3] += a.x * b.w;
            acc[1][0] += a.y * b.x; acc[1][1] += a.y * b.y;
            acc[1][2] += a.y * b.z; acc[1][3] += a.y * b.w;
            acc[2][0] += a.z * b.x; acc[2][1] += a.z * b.y;
            acc[2][2] += a.z * b.z; acc[2][3] += a.z * b.w;
            acc[3][0] += a.w * b.x; acc[3][1] += a.w * b.y;
            acc[3][2] += a.w * b.z; acc[3][3] += a.w * b.w;
        }
        __syncthreads();
    }

    const int col0 = n0 + tx * 4;
    const int h = col0 >> 6;
    const int dbase = col0 & 63;
    const float b0 = bias[col0 + 0];
    const float b1 = bias[col0 + 1];
    const float b2 = bias[col0 + 2];
    const float b3 = bias[col0 + 3];

#pragma unroll
    for (int i = 0; i < 4; i++) {
        const int m = m0 + ty * 4 + i;
        const int bidx = m >> 11;
        const int n = m & 2047;
        float v0 = acc[i][0] + b0;
        float v1 = acc[i][1] + b1;
        float v2 = acc[i][2] + b2;
        float v3 = acc[i][3] + b3;
        if (doRope) {
            const int f0 = dbase >> 1;
            const int f1 = f0 + 1;
            const float c0 = cosT[n * 32 + f0], s0 = sinT[n * 32 + f0];
            const float c1 = cosT[n * 32 + f1], s1 = sinT[n * 32 + f1];
            float r0 = v0, i0 = v1, r1 = v2, i1 = v3;
            v0 = r0 * c0 - i0 * s0;
            v1 = r0 * s0 + i0 * c0;
            v2 = r1 * c1 - i1 * s1;
            v3 = r1 * s1 + i1 * c1;
        }
        float4 o4 = make_float4(v0, v1, v2, v3);
        *(float4*)&outp[(((size_t)bidx * NHEADS + h) * N_ + n) * HD + dbase] = o4;
    }
}

// ===========================================================================
// TF32 flash-attention (single-pass, rna-rounded at staging).
// CTA: 128 queries, 8 warps (16q x 64keys each). Key tile 64.
// ===========================================================================
__global__ __launch_bounds__(256, 2) void attn_tf32_kernel(float* __restrict__ out)
{
    extern __shared__ float smf[];
    float* Qs = smf;                 // [128][36]  scaled, rounded
    float* Ks = Qs + 128 * 36;       // [64][36]
    float* Vs = Ks + 64 * 36;        // [64][72]
    float* Ps = Vs + 64 * 72;        // [128][72]

    const int tid  = threadIdx.x;
    const int wid  = tid >> 5;
    const int lane = tid & 31;
    const int r    = lane >> 2;
    const int c    = lane & 3;

    const int bh = blockIdx.y;
    const int q0 = blockIdx.x * 128;

    const float* __restrict__ Qg = g_scratch[0] + ((size_t)bh * N_ + q0) * HD;
    const float* __restrict__ Kg = g_scratch[1] + (size_t)bh * N_ * HD;
    const float* __restrict__ Vg = g_scratch[2] + (size_t)bh * N_ * HD;

    // ---- Stage Q (scaled by hd^-0.5 = 0.125), rounded ----
#pragma unroll
    for (int i = 0; i < 8; i++) {
        const int idx = tid + i * 256;       // 2048 float4
        const int row = idx >> 4;
        const int d0 = (idx & 15) * 4;
        float4 qv = *(const float4*)(Qg + row * HD + d0);
        Qs[row * 36 + d0 + 0] = to_tf32(qv.x * 0.125f);
        Qs[row * 36 + d0 + 1] = to_tf32(qv.y * 0.125f);
        Qs[row * 36 + d0 + 2] = to_tf32(qv.z * 0.125f);
        Qs[row * 36 + d0 + 3] = to_tf32(qv.w * 0.125f);
    }

    float oacc[8][4];
#pragma unroll
    for (int n = 0; n < 8; n++)
#pragma unroll
        for (int t = 0; t < 4; t++) oacc[n][t] = 0.f;
    float mrow0 = -1e30f, mrow1 = -1e30f;
    float lrow0 = 0.f, lrow1 = 0.f;

    const int qrow = wid * 16 + r;

    for (int kt = 0; kt < N_ / 64; kt++) {
        __syncthreads();
        const float* Kt = Kg + (size_t)kt * 64 * HD;
        const float* Vt = Vg + (size_t)kt * 64 * HD;
#pragma unroll
        for (int i = 0; i < 4; i++) {
            const int idx = tid + i * 256;   // 1024 float4
            const int row = idx >> 4;
            const int d0 = (idx & 15) * 4;
            float4 kv = *(const float4*)(Kt + row * HD + d0);
            Ks[row * 36 + d0 + 0] = to_tf32(kv.x);
            Ks[row * 36 + d0 + 1] = to_tf32(kv.y);
            Ks[row * 36 + d0 + 2] = to_tf32(kv.z);
            Ks[row * 36 + d0 + 3] = to_tf32(kv.w);
            float4 vv = *(const float4*)(Vt + row * HD + d0);
            Vs[row * 72 + d0 + 0] = to_tf32(vv.x);
            Vs[row * 72 + d0 + 1] = to_tf32(vv.y);
            Vs[row * 72 + d0 + 2] = to_tf32(vv.z);
            Vs[row * 72 + d0 + 3] = to_tf32(vv.w);
        }
        __syncthreads();

        // ---- S = Q K^T ----
        float sacc[8][4];
#pragma unroll
        for (int n = 0; n < 8; n++)
#pragma unroll
            for (int t = 0; t < 4; t++) sacc[n][t] = 0.f;

#pragma unroll
        for (int kf = 0; kf < 8; kf++) {
            const int d = kf * 8 + c;
            uint32_t af[4];
            af[0] = f2u(Qs[qrow * 36 + d]);
            af[1] = f2u(Qs[(qrow + 8) * 36 + d]);
            af[2] = f2u(Qs[qrow * 36 + d + 4]);
            af[3] = f2u(Qs[(qrow + 8) * 36 + d + 4]);
#pragma unroll
            for (int n = 0; n < 8; n++) {
                const int key = n * 8 + r;
                uint32_t bb[2];
                bb[0] = f2u(Ks[key * 36 + d]);
                bb[1] = f2u(Ks[key * 36 + d + 4]);
                mma_tf32(sacc[n], af, bb, sacc[n]);
            }
        }

        // ---- Warp-local online softmax ----
        float tmax0 = -1e30f, tmax1 = -1e30f;
#pragma unroll
        for (int n = 0; n < 8; n++) {
            tmax0 = fmaxf(tmax0, fmaxf(sacc[n][0], sacc[n][1]));
            tmax1 = fmaxf(tmax1, fmaxf(sacc[n][2], sacc[n][3]));
        }
        tmax0 = fmaxf(tmax0, __shfl_xor_sync(0xffffffffu, tmax0, 1));
        tmax0 = fmaxf(tmax0, __shfl_xor_sync(0xffffffffu, tmax0, 2));
        tmax1 = fmaxf(tmax1, __shfl_xor_sync(0xffffffffu, tmax1, 1));
        tmax1 = fmaxf(tmax1, __shfl_xor_sync(0xffffffffu, tmax1, 2));

        const float mn0 = fmaxf(mrow0, tmax0);
        const float mn1 = fmaxf(mrow1, tmax1);
        const float fac0 = __expf(mrow0 - mn0);
        const float fac1 = __expf(mrow1 - mn1);
        mrow0 = mn0; mrow1 = mn1;

        float rs0 = 0.f, rs1 = 0.f;
#pragma unroll
        for (int n = 0; n < 8; n++) {
            sacc[n][0] = __expf(sacc[n][0] - mn0);
            sacc[n][1] = __expf(sacc[n][1] - mn0);
            sacc[n][2] = __expf(sacc[n][2] - mn1);
            sacc[n][3] = __expf(sacc[n][3] - mn1);
            rs0 += sacc[n][0] + sacc[n][1];
            rs1 += sacc[n][2] + sacc[n][3];
        }
        rs0 += __shfl_xor_sync(0xffffffffu, rs0, 1);
        rs0 += __shfl_xor_sync(0xffffffffu, rs0, 2);
        rs1 += __shfl_xor_sync(0xffffffffu, rs1, 1);
        rs1 += __shfl_xor_sync(0xffffffffu, rs1, 2);
        lrow0 = lrow0 * fac0 + rs0;
        lrow1 = lrow1 * fac1 + rs1;

#pragma unroll
        for (int n = 0; n < 8; n++) {
            oacc[n][0] *= fac0; oacc[n][1] *= fac0;
            oacc[n][2] *= fac1; oacc[n][3] *= fac1;
        }

        // ---- Stage P (warp-private rows), rounded ----
#pragma unroll
        for (int n = 0; n < 8; n++) {
            const int col = n * 8 + 2 * c;
            Ps[qrow * 72 + col]           = to_tf32(sacc[n][0]);
            Ps[qrow * 72 + col + 1]       = to_tf32(sacc[n][1]);
            Ps[(qrow + 8) * 72 + col]     = to_tf32(sacc[n][2]);
            Ps[(qrow + 8) * 72 + col + 1] = to_tf32(sacc[n][3]);
        }
        __syncwarp();

        // ---- O += P V ----
#pragma unroll
        for (int kf = 0; kf < 8; kf++) {
            const int kcol = kf * 8 + c;
            uint32_t pa[4];
            pa[0] = f2u(Ps[qrow * 72 + kcol]);
            pa[1] = f2u(Ps[(qrow + 8) * 72 + kcol]);
            pa[2] = f2u(Ps[qrow * 72 + kcol + 4]);
            pa[3] = f2u(Ps[(qrow + 8) * 72 + kcol + 4]);
#pragma unroll
            for (int n = 0; n < 8; n++) {
                uint32_t bb[2];
                const int d = n * 8 + r;
                bb[0] = f2u(Vs[(kf * 8 + c) * 72 + d]);
                bb[1] = f2u(Vs[(kf * 8 + c + 4) * 72 + d]);
                mma_tf32(oacc[n], pa, bb, oacc[n]);
            }
        }
    }

    const int b = bh >> 4;
    const int h = bh & 15;
    const float inv0 = 1.0f / lrow0;
    const float inv1 = 1.0f / lrow1;
    const int row0 = q0 + wid * 16 + r;
#pragma unroll
    for (int n = 0; n < 8; n++) {
        const int d = n * 8 + 2 * c;
        *(float2*)&out[((size_t)b * N_ + row0) * C_ + h * HD + d] =
            make_float2(oacc[n][0] * inv0, oacc[n][1] * inv0);
        *(float2*)&out[((size_t)b * N_ + row0 + 8) * C_ + h * HD + d] =
            make_float2(oacc[n][2] * inv1, oacc[n][3] * inv1);
    }
}

// ===========================================================================
// Attention checker: one block per sampled row (128 blocks, 256 threads).
// ===========================================================================
__global__ __launch_bounds__(256) void attn_check_kernel(const float* __restrict__ out)
{
    __shared__ float qs[HD];
    __shared__ float sc[N_];
    __shared__ float red[64];
    __shared__ float mx_s, l_s;
    __shared__ float ored[4][HD];

    const int tid = threadIdx.x;
    const int s  = blockIdx.x;       // 0..127
    const int bh = s & 31;
    const int q  = (s * 997 + 13) & 2047;

    const float* Qr = g_scratch[0] + ((size_t)bh * N_ + q) * HD;
    const float* Kg = g_scratch[1] + (size_t)bh * N_ * HD;
    const float* Vg = g_scratch[2] + (size_t)bh * N_ * HD;

    if (tid < HD) qs[tid] = Qr[tid] * 0.125f;
    __syncthreads();

#pragma unroll 1
    for (int u = 0; u < 8; u++) {
        const int key = tid * 8 + u;
        const float* Kr = Kg + (size_t)key * HD;
        float a = 0.f, b2 = 0.f;
#pragma unroll
        for (int d = 0; d < HD; d += 2) { a += qs[d] * Kr[d]; b2 += qs[d + 1] * Kr[d + 1]; }
        sc[key] = a + b2;
    }
    __syncthreads();

    float m = -1e30f;
    for (int i = tid; i < N_; i += 256) m = fmaxf(m, sc[i]);
#pragma unroll
    for (int off = 16; off >= 1; off >>= 1)
        m = fmaxf(m, __shfl_xor_sync(0xffffffffu, m, off));
    if ((tid & 31) == 0) red[tid >> 5] = m;
    __syncthreads();
    if (tid == 0) {
        float mm = red[0];
        for (int i = 1; i < 8; i++) mm = fmaxf(mm, red[i]);
        mx_s = mm;
    }
    __syncthreads();
    const float mx = mx_s;

    float ls = 0.f;
    for (int i = tid; i < N_; i += 256) {
        const float p = __expf(sc[i] - mx);
        sc[i] = p;
        ls += p;
    }
#pragma unroll
    for (int off = 16; off >= 1; off >>= 1)
        ls += __shfl_xor_sync(0xffffffffu, ls, off);
    if ((tid & 31) == 0) red[tid >> 5] = ls;
    __syncthreads();
    if (tid == 0) {
        float ll = 0.f;
        for (int i = 0; i < 8; i++) ll += red[i];
        l_s = ll;
    }
    __syncthreads();
    const float l = l_s;

    const int d = tid & 63;
    const int chunk = tid >> 6;
    float part = 0.f;
    const int k0 = chunk * 512;
    for (int key = k0; key < k0 + 512; key++)
        part += sc[key] * Vg[(size_t)key * HD + d];
    ored[chunk][d] = part;
    __syncthreads();

    if (tid < HD) {
        const float o = (ored[0][tid] + ored[1][tid]) + (ored[2][tid] + ored[3][tid]);
        const float ref = o / l;
        const int b = bh >> 4;
        const int h = bh & 15;
        const float got = out[((size_t)b * N_ + q) * C_ + h * HD + tid];
        if (!(fabsf(got - ref) <= 5e-3f * (fabsf(ref) + 1.f)))
            atomicOr(&g_bad[1], 1);
    }
}

// ===========================================================================
// Fallback attention (round-2 FFMA, known good), gated on g_bad[1].
// ===========================================================================
__global__ __launch_bounds__(256) void attn_fix_kernel(float* __restrict__ out)
{
    if (g_bad[1] == 0) return;

    extern __shared__ float sm[];
    float* Qs = sm;                 // [64][68]
    float* Ks = Qs + 64 * 68;       // [64][68]
    float* Vs = Ks + 64 * 68;       // [64][68]
    float* Ps = Vs + 64 * 68;       // [64][65]

    const int tid = threadIdx.x;
    const int tx = tid & 15;
    const int ty = tid >> 4;
    const int bh = blockIdx.y;
    const int q0 = blockIdx.x * 64;

    const float* __restrict__ Qg = g_scratch[0] + ((size_t)bh * N_ + q0) * HD;
    const float* __restrict__ Kg = g_scratch[1] + (size_t)bh * N_ * HD;
    const float* __restrict__ Vg = g_scratch[2] + (size_t)bh * N_ * HD;

    const int lr = tid >> 2;
    const int lc = (tid & 3) * 16;

#pragma unroll
    for (int u = 0; u < 4; u++) {
        const int d = lc + u * 4;
        float4 qv = *(const float4*)(Qg + lr * HD + d);
        Qs[(d + 0) * 68 + lr] = qv.x;
        Qs[(d + 1) * 68 + lr] = qv.y;
        Qs[(d + 2) * 68 + lr] = qv.z;
        Qs[(d + 3) * 68 + lr] = qv.w;
    }

    float o[4][4] = {};
    float mrow[4] = {-1e30f, -1e30f, -1e30f, -1e30f};
    float lrow[4] = {0.f, 0.f, 0.f, 0.f};
    const float scale = 0.125f;

    for (int kt = 0; kt < N_ / 64; kt++) {
        __syncthreads();
        const float* Kt = Kg + (size_t)kt * 64 * HD;
        const float* Vt = Vg + (size_t)kt * 64 * HD;
#pragma unroll
        for (int u = 0; u < 4; u++) {
            const int d = lc + u * 4;
            float4 kv = *(const float4*)(Kt + lr * HD + d);
            Ks[(d + 0) * 68 + lr] = kv.x;
            Ks[(d + 1) * 68 + lr] = kv.y;
            Ks[(d + 2) * 68 + lr] = kv.z;
            Ks[(d + 3) * 68 + lr] = kv.w;
            float4 vv = *(const float4*)(Vt + lr * HD + d);
            *(float4*)&Vs[lr * 68 + d] = vv;
        }
        __syncthreads();

        float s[4][4] = {};
#pragma unroll 16
        for (int kk = 0; kk < 64; kk++) {
            float4 a = *(const float4*)&Qs[kk * 68 + ty * 4];
            float4 b = *(const float4*)&Ks[kk * 68 + tx * 4];
            s[0][0] += a.x * b.x; s[0][1] += a.x * b.y;
            s[0][2] += a.x * b.z; s[0][3] += a.x * b.w;
            s[1][0] += a.y * b.x; s[1][1] += a.y * b.y;
            s[1][2] += a.y * b.z; s[1][3] += a.y * b.w;
            s[2][0] += a.z * b.x; s[2][1] += a.z * b.y;
            s[2][2] += a.z * b.z; s[2][3] += a.z * b.w;
            s[3][0] += a.w * b.x; s[3][1] += a.w * b.y;
            s[3][2] += a.w * b.z; s[3][3] += a.w * b.w;
        }

#pragma unroll
        for (int i = 0; i < 4; i++) {
            float s0 = s[i][0] * scale;
            float s1 = s[i][1] * scale;
            float s2 = s[i][2] * scale;
            float s3 = s[i][3] * scale;
            float rm = fmaxf(fmaxf(s0, s1), fmaxf(s2, s3));
#pragma unroll
            for (int off = 1; off < 16; off <<= 1)
                rm = fmaxf(rm, __shfl_xor_sync(0xffffffffu, rm, off));
            const float mn = fmaxf(mrow[i], rm);
            const float fac = __expf(mrow[i] - mn);
            float p0 = __expf(s0 - mn);
            float p1 = __expf(s1 - mn);
            float p2 = __expf(s2 - mn);
            float p3 = __expf(s3 - mn);
            float rs = p0 + p1 + p2 + p3;
#pragma unroll
            for (int off = 1; off < 16; off <<= 1)
                rs += __shfl_xor_sync(0xffffffffu, rs, off);
            lrow[i] = lrow[i] * fac + rs;
            mrow[i] = mn;
            o[i][0] *= fac; o[i][1] *= fac; o[i][2] *= fac; o[i][3] *= fac;
            s[i][0] = p0; s[i][1] = p1; s[i][2] = p2; s[i][3] = p3;
        }

#pragma unroll
        for (int j = 0; j < 4; j++)
#pragma unroll
            for (int i = 0; i < 4; i++)
                Ps[(tx * 4 + j) * 65 + ty * 4 + i] = s[i][j];
        __syncthreads();

#pragma unroll 16
        for (int kk = 0; kk < 64; kk++) {
            float a0 = Ps[kk * 65 + ty * 4 + 0];
            float a1 = Ps[kk * 65 + ty * 4 + 1];
            float a2 = Ps[kk * 65 + ty * 4 + 2];
            float a3 = Ps[kk * 65 + ty * 4 + 3];
            float4 b = *(const float4*)&Vs[kk * 68 + tx * 4];
            o[0][0] += a0 * b.x; o[0][1] += a0 * b.y;
            o[0][2] += a0 * b.z; o[0][3] += a0 * b.w;
            o[1][0] += a1 * b.x; o[1][1] += a1 * b.y;
            o[1][2] += a1 * b.z; o[1][3] += a1 * b.w;
            o[2][0] += a2 * b.x; o[2][1] += a2 * b.y;
            o[2][2] += a2 * b.z; o[2][3] += a2 * b.w;
            o[3][0] += a3 * b.x; o[3][1] += a3 * b.y;
            o[3][2] += a3 * b.z; o[3][3] += a3 * b.w;
        }
    }

    const int b = bh >> 4;
    const int h = bh & 15;
#pragma unroll
    for (int i = 0; i < 4; i++) {
        const int n = q0 + ty * 4 + i;
        const float inv = 1.0f / lrow[i];
        float4 ov = make_float4(o[i][0] * inv, o[i][1] * inv,
                                o[i][2] * inv, o[i][3] * inv);
        *(float4*)&out[((size_t)b * N_ + n) * C_ + h * HD + tx * 4] = ov;
    }
}

// ---------------------------------------------------------------------------
// Launch
// ---------------------------------------------------------------------------
extern "C" void kernel_launch(void* const* d_in, const int* in_sizes, int n_in,
                              void* d_out, int out_size)
{
    const float* q    = (const float*)d_in[0];
    const float* k    = (const float*)d_in[1];
    const float* v    = (const float*)d_in[2];
    const float* qcos = (const float*)d_in[3];
    const float* qsin = (const float*)d_in[4];
    const float* Wq   = (const float*)d_in[7];
    const float* bq   = (const float*)d_in[8];
    const float* Wk   = (const float*)d_in[9];
    const float* bk   = (const float*)d_in[10];
    const float* Wv   = (const float*)d_in[11];
    const float* bv   = (const float*)d_in[12];
    float* out = (float*)d_out;

    reset_kernel<<<1, 32>>>();

    const int proj_smem = 2 * 128 * 36 * (int)sizeof(float);    // 36864 B
    cudaFuncSetAttribute(proj_tf32_kernel,
                         cudaFuncAttributeMaxDynamicSharedMemorySize, proj_smem);
    proj_tf32_kernel<<<dim3(C_ / 128, (B_ * N_) / 128, 3), 256, proj_smem>>>(
        q, k, v, Wq, Wk, Wv, bq, bk, bv, qcos, qsin);

    proj_check_kernel<<<3, 256>>>(q, k, v, Wq, Wk, Wv, bq, bk, bv, qcos, qsin);

    dim3 gfix(C_ / 64, (B_ * N_) / 64);
    proj_fix_kernel<<<gfix, 256>>>(q, Wq, bq, qcos, qsin, 0, 1);
    proj_fix_kernel<<<gfix, 256>>>(k, Wk, bk, qcos, qsin, 1, 1);
    proj_fix_kernel<<<gfix, 256>>>(v, Wv, bv, nullptr, nullptr, 2, 0);

    const int attn_smem = (128 * 36 + 64 * 36 + 64 * 72 + 128 * 72)
                        * (int)sizeof(float);                   // 82944 B
    cudaFuncSetAttribute(attn_tf32_kernel,
                         cudaFuncAttributeMaxDynamicSharedMemorySize, attn_smem);
    attn_tf32_kernel<<<dim3(N_ / 128, B_ * NHEADS), 256, attn_smem>>>(out);

    attn_check_kernel<<<128, 256>>>(out);

    const int fix_smem = (64 * 68 * 3 + 64 * 65) * (int)sizeof(float);
    cudaFuncSetAttribute(attn_fix_kernel,
                         cudaFuncAttributeMaxDynamicSharedMemorySize, fix_smem);
    attn_fix_kernel<<<dim3(N_ / 64, B_ * NHEADS), 256, fix_smem>>>(out);
}

// round 14
// speedup vs baseline: 1.9115x; 1.0293x over previous
#include <cuda_runtime.h>
#include <cstdint>

#define NHEADS 16
#define B_     2
#define N_     2048
#define C_     1024
#define HD     64

__device__ float g_scratch[3][B_ * NHEADS * N_ * HD];
__device__ int g_bad[2];

__device__ __forceinline__ uint32_t tf32_bits(float x) {
    uint32_t r;
    asm("cvt.rna.tf32.f32 %0, %1;" : "=r"(r) : "f"(x));
    return r;
}
__device__ __forceinline__ float to_tf32(float x) {
    return __uint_as_float(tf32_bits(x));
}
__device__ __forceinline__ void mma_tf32(float* d, const uint32_t* a,
                                         const uint32_t* b, const float* c) {
    asm volatile(
        "mma.sync.aligned.m16n8k8.row.col.f32.tf32.tf32.f32 "
        "{%0,%1,%2,%3}, {%4,%5,%6,%7}, {%8,%9}, {%10,%11,%12,%13};"
        : "=f"(d[0]), "=f"(d[1]), "=f"(d[2]), "=f"(d[3])
        : "r"(a[0]), "r"(a[1]), "r"(a[2]), "r"(a[3]),
          "r"(b[0]), "r"(b[1]),
          "f"(c[0]), "f"(c[1]), "f"(c[2]), "f"(c[3]));
}
__device__ __forceinline__ uint32_t f2u(float x) { return __float_as_uint(x); }

__global__ void reset_kernel() { if (threadIdx.x < 2) g_bad[threadIdx.x] = 0; }
__global__ void noop_kernel() {}

// ===========================================================================
// TF32 projection (round-11, known good): CTA 128x128, warp 64x32.
// ===========================================================================
__global__ __launch_bounds__(256, 2) void proj_tf32_kernel(
    const float* __restrict__ Xq, const float* __restrict__ Xk,
    const float* __restrict__ Xv,
    const float* __restrict__ Wq, const float* __restrict__ Wk,
    const float* __restrict__ Wv,
    const float* __restrict__ bq, const float* __restrict__ bk,
    const float* __restrict__ bv,
    const float* __restrict__ cosT, const float* __restrict__ sinT)
{
    extern __shared__ float smemf[];
    float* As = smemf;               // [128][36]
    float* Bs = As + 128 * 36;       // [128][36]

    const int which = blockIdx.z;
    const float* __restrict__ X    = which == 0 ? Xq : (which == 1 ? Xk : Xv);
    const float* __restrict__ W    = which == 0 ? Wq : (which == 1 ? Wk : Wv);
    const float* __restrict__ bias = which == 0 ? bq : (which == 1 ? bk : bv);
    const int doRope = (which != 2);
    float* __restrict__ outp = g_scratch[which];

    const int tid  = threadIdx.x;
    const int wid  = tid >> 5;
    const int lane = tid & 31;
    const int r    = lane >> 2;
    const int c    = lane & 3;
    const int wm   = wid & 1;
    const int wn   = wid >> 1;

    const int m0 = blockIdx.y * 128;
    const int n0 = blockIdx.x * 128;

    const int lrow = tid >> 3;
    const int lkf  = (tid & 7) * 4;

    float acc[4][4][4];
#pragma unroll
    for (int i = 0; i < 4; i++)
#pragma unroll
        for (int j = 0; j < 4; j++)
#pragma unroll
            for (int t = 0; t < 4; t++) acc[i][j][t] = 0.f;

    for (int kc = 0; kc < C_; kc += 32) {
#pragma unroll
        for (int p = 0; p < 4; p++) {
            const int row = lrow + p * 32;
            float4 av  = *(const float4*)(X + (size_t)(m0 + row) * C_ + kc + lkf);
            float4 bv4 = *(const float4*)(W + (size_t)(n0 + row) * C_ + kc + lkf);
            As[row * 36 + lkf + 0] = to_tf32(av.x);
            As[row * 36 + lkf + 1] = to_tf32(av.y);
            As[row * 36 + lkf + 2] = to_tf32(av.z);
            As[row * 36 + lkf + 3] = to_tf32(av.w);
            Bs[row * 36 + lkf + 0] = to_tf32(bv4.x);
            Bs[row * 36 + lkf + 1] = to_tf32(bv4.y);
            Bs[row * 36 + lkf + 2] = to_tf32(bv4.z);
            Bs[row * 36 + lkf + 3] = to_tf32(bv4.w);
        }
        __syncthreads();

#pragma unroll
        for (int ks = 0; ks < 4; ks++) {
            const int kb = ks * 8;
            uint32_t bf[4][2];
#pragma unroll
            for (int nf = 0; nf < 4; nf++) {
                const int nrow = wn * 32 + nf * 8 + r;
                bf[nf][0] = f2u(Bs[nrow * 36 + kb + c]);
                bf[nf][1] = f2u(Bs[nrow * 36 + kb + c + 4]);
            }
#pragma unroll
            for (int mf = 0; mf < 4; mf++) {
                const int mrow = wm * 64 + mf * 16 + r;
                uint32_t af[4];
                af[0] = f2u(As[mrow * 36 + kb + c]);
                af[1] = f2u(As[(mrow + 8) * 36 + kb + c]);
                af[2] = f2u(As[mrow * 36 + kb + c + 4]);
                af[3] = f2u(As[(mrow + 8) * 36 + kb + c + 4]);
#pragma unroll
                for (int nf = 0; nf < 4; nf++)
                    mma_tf32(acc[mf][nf], af, bf[nf], acc[mf][nf]);
            }
        }
        __syncthreads();
    }

#pragma unroll
    for (int nf = 0; nf < 4; nf++) {
        const int col = n0 + wn * 32 + nf * 8 + 2 * c;
        const int h = col >> 6;
        const int dbase = col & 63;
        const int f = dbase >> 1;
        const float bias0 = bias[col];
        const float bias1 = bias[col + 1];
#pragma unroll
        for (int mf = 0; mf < 4; mf++) {
#pragma unroll
            for (int half = 0; half < 2; half++) {
                const int m = m0 + wm * 64 + mf * 16 + r + half * 8;
                const int bidx = m >> 11;
                const int n = m & 2047;
                float v0 = acc[mf][nf][half * 2 + 0] + bias0;
                float v1 = acc[mf][nf][half * 2 + 1] + bias1;
                if (doRope) {
                    const float cs = cosT[n * 32 + f];
                    const float sn = sinT[n * 32 + f];
                    const float rr = v0, ri = v1;
                    v0 = rr * cs - ri * sn;
                    v1 = rr * sn + ri * cs;
                }
                *(float2*)&outp[(((size_t)bidx * NHEADS + h) * N_ + n) * HD + dbase] =
                    make_float2(v0, v1);
            }
        }
    }
}

// ===========================================================================
// Proj checker (fp32 recompute of 768 samples)
// ===========================================================================
__global__ void proj_check_kernel(
    const float* __restrict__ Xq, const float* __restrict__ Xk,
    const float* __restrict__ Xv,
    const float* __restrict__ Wq, const float* __restrict__ Wk,
    const float* __restrict__ Wv,
    const float* __restrict__ bq, const float* __restrict__ bk,
    const float* __restrict__ bv,
    const float* __restrict__ cosT, const float* __restrict__ sinT)
{
    const int which = blockIdx.x;
    const float* __restrict__ X    = which == 0 ? Xq : (which == 1 ? Xk : Xv);
    const float* __restrict__ W    = which == 0 ? Wq : (which == 1 ? Wk : Wv);
    const float* __restrict__ bias = which == 0 ? bq : (which == 1 ? bk : bv);

    const int t = threadIdx.x;
    const int m   = (t * 521 + which * 1365) & 4095;
    const int col = (t * 1031 + which * 342) & 1022;

    float s0a = 0.f, s0b = 0.f, s1a = 0.f, s1b = 0.f;
    const float* Xr = X + (size_t)m * C_;
    const float* W0 = W + (size_t)col * C_;
    const float* W1 = W + (size_t)(col + 1) * C_;
    for (int kk = 0; kk < C_; kk += 4) {
        float4 xv = *(const float4*)(Xr + kk);
        float4 w0 = *(const float4*)(W0 + kk);
        float4 w1 = *(const float4*)(W1 + kk);
        s0a += xv.x * w0.x + xv.y * w0.y;
        s0b += xv.z * w0.z + xv.w * w0.w;
        s1a += xv.x * w1.x + xv.y * w1.y;
        s1b += xv.z * w1.z + xv.w * w1.w;
    }
    float s0 = s0a + s0b + bias[col];
    float s1 = s1a + s1b + bias[col + 1];

    const int n = m & 2047, b = m >> 11, h = col >> 6, d = col & 63;
    if (which != 2) {
        const float cs = cosT[n * 32 + (d >> 1)];
        const float sn = sinT[n * 32 + (d >> 1)];
        const float rr = s0, ri = s1;
        s0 = rr * cs - ri * sn;
        s1 = rr * sn + ri * cs;
    }
    const float g0 = g_scratch[which][(((size_t)b * NHEADS + h) * N_ + n) * HD + d];
    const float g1 = g_scratch[which][(((size_t)b * NHEADS + h) * N_ + n) * HD + d + 1];
    const bool ok0 = fabsf(g0 - s0) <= 5e-3f * (fabsf(s0) + 1.f);
    const bool ok1 = fabsf(g1 - s1) <= 5e-3f * (fabsf(s1) + 1.f);
    if (!(ok0 && ok1)) atomicOr(&g_bad[0], 1);
}

// ===========================================================================
// Fallback projection (FFMA, known good), gated; z selects {Q,K,V}.
// ===========================================================================
__global__ __launch_bounds__(256) void proj_fix_kernel(
    const float* __restrict__ Xq, const float* __restrict__ Xk,
    const float* __restrict__ Xv,
    const float* __restrict__ Wq, const float* __restrict__ Wk,
    const float* __restrict__ Wv,
    const float* __restrict__ bq, const float* __restrict__ bk,
    const float* __restrict__ bv,
    const float* __restrict__ cosT, const float* __restrict__ sinT)
{
    if (g_bad[0] == 0) return;

    __shared__ float As[16][68];
    __shared__ float Bs[16][68];

    const int which = blockIdx.z;
    const float* __restrict__ X    = which == 0 ? Xq : (which == 1 ? Xk : Xv);
    const float* __restrict__ W    = which == 0 ? Wq : (which == 1 ? Wk : Wv);
    const float* __restrict__ bias = which == 0 ? bq : (which == 1 ? bk : bv);
    const int doRope = (which != 2);
    float* __restrict__ outp = g_scratch[which];

    const int tid = threadIdx.x;
    const int tx = tid & 15;
    const int ty = tid >> 4;
    const int m0 = blockIdx.y * 64;
    const int n0 = blockIdx.x * 64;

    const int lr = tid >> 2;
    const int lk = (tid & 3) * 4;

    const float* Arow = X + (size_t)(m0 + lr) * C_;
    const float* Brow = W + (size_t)(n0 + lr) * C_;

    float acc[4][4] = {};

    for (int k0 = 0; k0 < C_; k0 += 16) {
        float4 av = *(const float4*)(Arow + k0 + lk);
        float4 bv4 = *(const float4*)(Brow + k0 + lk);
        As[lk + 0][lr] = av.x; As[lk + 1][lr] = av.y;
        As[lk + 2][lr] = av.z; As[lk + 3][lr] = av.w;
        Bs[lk + 0][lr] = bv4.x; Bs[lk + 1][lr] = bv4.y;
        Bs[lk + 2][lr] = bv4.z; Bs[lk + 3][lr] = bv4.w;
        __syncthreads();
#pragma unroll
        for (int kk = 0; kk < 16; kk++) {
            float4 a = *(const float4*)&As[kk][ty * 4];
            float4 b = *(const float4*)&Bs[kk][tx * 4];
            acc[0][0] += a.x * b.x; acc[0][1] += a.x * b.y;
            acc[0][2] += a.x * b.z; acc[0][3] += a.x * b.w;
            acc[1][0] += a.y * b.x; acc[1][1] += a.y * b.y;
            acc[1][2] += a.y * b.z; acc[1][3] += a.y * b.w;
            acc[2][0] += a.z * b.x; acc[2][1] += a.z * b.y;
            acc[2][2] += a.z * b.z; acc[2][3] += a.z * b.w;
            acc[3][0] += a.w * b.x; acc[3][1] += a.w * b.y;
            acc[3][2] += a.w * b.z; acc[3][3] += a.w * b.w;
        }
        __syncthreads();
    }

    const int col0 = n0 + tx * 4;
    const int h = col0 >> 6;
    const int dbase = col0 & 63;
    const float b0 = bias[col0 + 0];
    const float b1 = bias[col0 + 1];
    const float b2 = bias[col0 + 2];
    const float b3 = bias[col0 + 3];

#pragma unroll
    for (int i = 0; i < 4; i++) {
        const int m = m0 + ty * 4 + i;
        const int bidx = m >> 11;
        const int n = m & 2047;
        float v0 = acc[i][0] + b0;
        float v1 = acc[i][1] + b1;
        float v2 = acc[i][2] + b2;
        float v3 = acc[i][3] + b3;
        if (doRope) {
            const int f0 = dbase >> 1;
            const int f1 = f0 + 1;
            const float c0 = cosT[n * 32 + f0], s0 = sinT[n * 32 + f0];
            const float c1 = cosT[n * 32 + f1], s1 = sinT[n * 32 + f1];
            float r0 = v0, i0 = v1, r1 = v2, i1 = v3;
            v0 = r0 * c0 - i0 * s0;
            v1 = r0 * s0 + i0 * c0;
            v2 = r1 * c1 - i1 * s1;
            v3 = r1 * s1 + i1 * c1;
        }
        float4 o4 = make_float4(v0, v1, v2, v3);
        *(float4*)&outp[(((size_t)bidx * NHEADS + h) * N_ + n) * HD + dbase] = o4;
    }
}

// ===========================================================================
// TF32 flash-attention v2: 128 threads, 4 warps, warp tile 32q x 64k.
// B-fragments feed two mma each (mf=0/1). Q frags in registers.
// ===========================================================================
__global__ __launch_bounds__(128, 2) void attn_tf32_kernel(float* __restrict__ out)
{
    extern __shared__ float smf[];
    float* Qs = smf;                 // [128][36]
    float* Ks = Qs + 128 * 36;       // [64][36]
    float* Vs = Ks + 64 * 36;        // [64][72]
    float* Ps = Vs + 64 * 72;        // [128][72]

    const int tid  = threadIdx.x;
    const int wid  = tid >> 5;       // 0..3
    const int lane = tid & 31;
    const int r    = lane >> 2;
    const int c    = lane & 3;

    const int bh = blockIdx.y;
    const int q0 = blockIdx.x * 128;

    const float* __restrict__ Qg = g_scratch[0] + ((size_t)bh * N_ + q0) * HD;
    const float* __restrict__ Kg = g_scratch[1] + (size_t)bh * N_ * HD;
    const float* __restrict__ Vg = g_scratch[2] + (size_t)bh * N_ * HD;

    // ---- Stage Q (scaled, rounded): 2048 float4, 16/thread ----
#pragma unroll
    for (int i = 0; i < 16; i++) {
        const int idx = tid + i * 128;
        const int row = idx >> 4;
        const int d0 = (idx & 15) * 4;
        float4 qv = *(const float4*)(Qg + row * HD + d0);
        Qs[row * 36 + d0 + 0] = to_tf32(qv.x * 0.125f);
        Qs[row * 36 + d0 + 1] = to_tf32(qv.y * 0.125f);
        Qs[row * 36 + d0 + 2] = to_tf32(qv.z * 0.125f);
        Qs[row * 36 + d0 + 3] = to_tf32(qv.w * 0.125f);
    }
    __syncthreads();

    // Q fragments: warp owns rows [wid*32, wid*32+32) = 2 m-tiles of 16
    const int qbase = wid * 32;
    uint32_t qa[2][8][4];
#pragma unroll
    for (int mf = 0; mf < 2; mf++) {
        const int qrow = qbase + mf * 16 + r;
#pragma unroll
        for (int kf = 0; kf < 8; kf++) {
            const int d = kf * 8 + c;
            qa[mf][kf][0] = f2u(Qs[qrow * 36 + d]);
            qa[mf][kf][1] = f2u(Qs[(qrow + 8) * 36 + d]);
            qa[mf][kf][2] = f2u(Qs[qrow * 36 + d + 4]);
            qa[mf][kf][3] = f2u(Qs[(qrow + 8) * 36 + d + 4]);
        }
    }

    float oacc[2][8][4];
#pragma unroll
    for (int mf = 0; mf < 2; mf++)
#pragma unroll
        for (int n = 0; n < 8; n++)
#pragma unroll
            for (int t = 0; t < 4; t++) oacc[mf][n][t] = 0.f;
    float mrow[2][2] = {{-1e30f, -1e30f}, {-1e30f, -1e30f}};
    float lrow[2][2] = {{0.f, 0.f}, {0.f, 0.f}};

    for (int kt = 0; kt < N_ / 64; kt++) {
        __syncthreads();
        const float* Kt = Kg + (size_t)kt * 64 * HD;
        const float* Vt = Vg + (size_t)kt * 64 * HD;
        // stage K/V: 1024 float4, 8/thread
#pragma unroll
        for (int i = 0; i < 8; i++) {
            const int idx = tid + i * 128;
            const int row = idx >> 4;
            const int d0 = (idx & 15) * 4;
            float4 kv = *(const float4*)(Kt + row * HD + d0);
            Ks[row * 36 + d0 + 0] = to_tf32(kv.x);
            Ks[row * 36 + d0 + 1] = to_tf32(kv.y);
            Ks[row * 36 + d0 + 2] = to_tf32(kv.z);
            Ks[row * 36 + d0 + 3] = to_tf32(kv.w);
            float4 vv = *(const float4*)(Vt + row * HD + d0);
            Vs[row * 72 + d0 + 0] = to_tf32(vv.x);
            Vs[row * 72 + d0 + 1] = to_tf32(vv.y);
            Vs[row * 72 + d0 + 2] = to_tf32(vv.z);
            Vs[row * 72 + d0 + 3] = to_tf32(vv.w);
        }
        __syncthreads();

        // ---- S = Q K^T : each B-fragment feeds 2 mma ----
        float sacc[2][8][4];
#pragma unroll
        for (int mf = 0; mf < 2; mf++)
#pragma unroll
            for (int n = 0; n < 8; n++)
#pragma unroll
                for (int t = 0; t < 4; t++) sacc[mf][n][t] = 0.f;

#pragma unroll
        for (int kf = 0; kf < 8; kf++) {
            const int d = kf * 8 + c;
#pragma unroll
            for (int n = 0; n < 8; n++) {
                const int key = n * 8 + r;
                uint32_t bb[2];
                bb[0] = f2u(Ks[key * 36 + d]);
                bb[1] = f2u(Ks[key * 36 + d + 4]);
                mma_tf32(sacc[0][n], qa[0][kf], bb, sacc[0][n]);
                mma_tf32(sacc[1][n], qa[1][kf], bb, sacc[1][n]);
            }
        }

        // ---- Online softmax (4 independent rows per thread) ----
#pragma unroll
        for (int mf = 0; mf < 2; mf++) {
            float tm0 = -1e30f, tm1 = -1e30f;
#pragma unroll
            for (int n = 0; n < 8; n++) {
                tm0 = fmaxf(tm0, fmaxf(sacc[mf][n][0], sacc[mf][n][1]));
                tm1 = fmaxf(tm1, fmaxf(sacc[mf][n][2], sacc[mf][n][3]));
            }
            tm0 = fmaxf(tm0, __shfl_xor_sync(0xffffffffu, tm0, 1));
            tm0 = fmaxf(tm0, __shfl_xor_sync(0xffffffffu, tm0, 2));
            tm1 = fmaxf(tm1, __shfl_xor_sync(0xffffffffu, tm1, 1));
            tm1 = fmaxf(tm1, __shfl_xor_sync(0xffffffffu, tm1, 2));

            const float mn0 = fmaxf(mrow[mf][0], tm0);
            const float mn1 = fmaxf(mrow[mf][1], tm1);
            const float fac0 = __expf(mrow[mf][0] - mn0);
            const float fac1 = __expf(mrow[mf][1] - mn1);
            mrow[mf][0] = mn0; mrow[mf][1] = mn1;

            float rs0 = 0.f, rs1 = 0.f;
#pragma unroll
            for (int n = 0; n < 8; n++) {
                sacc[mf][n][0] = __expf(sacc[mf][n][0] - mn0);
                sacc[mf][n][1] = __expf(sacc[mf][n][1] - mn0);
                sacc[mf][n][2] = __expf(sacc[mf][n][2] - mn1);
                sacc[mf][n][3] = __expf(sacc[mf][n][3] - mn1);
                rs0 += sacc[mf][n][0] + sacc[mf][n][1];
                rs1 += sacc[mf][n][2] + sacc[mf][n][3];
            }
            rs0 += __shfl_xor_sync(0xffffffffu, rs0, 1);
            rs0 += __shfl_xor_sync(0xffffffffu, rs0, 2);
            rs1 += __shfl_xor_sync(0xffffffffu, rs1, 1);
            rs1 += __shfl_xor_sync(0xffffffffu, rs1, 2);
            lrow[mf][0] = lrow[mf][0] * fac0 + rs0;
            lrow[mf][1] = lrow[mf][1] * fac1 + rs1;

#pragma unroll
            for (int n = 0; n < 8; n++) {
                oacc[mf][n][0] *= fac0; oacc[mf][n][1] *= fac0;
                oacc[mf][n][2] *= fac1; oacc[mf][n][3] *= fac1;
            }

            // Stage P (warp-private rows), rounded
            const int qrow = qbase + mf * 16 + r;
#pragma unroll
            for (int n = 0; n < 8; n++) {
                const int col = n * 8 + 2 * c;
                Ps[qrow * 72 + col]           = to_tf32(sacc[mf][n][0]);
                Ps[qrow * 72 + col + 1]       = to_tf32(sacc[mf][n][1]);
                Ps[(qrow + 8) * 72 + col]     = to_tf32(sacc[mf][n][2]);
                Ps[(qrow + 8) * 72 + col + 1] = to_tf32(sacc[mf][n][3]);
            }
        }
        __syncwarp();

        // ---- O += P V : each V-fragment feeds 2 mma ----
#pragma unroll
        for (int kf = 0; kf < 8; kf++) {
            const int kcol = kf * 8 + c;
            uint32_t pa[2][4];
#pragma unroll
            for (int mf = 0; mf < 2; mf++) {
                const int qrow = qbase + mf * 16 + r;
                pa[mf][0] = f2u(Ps[qrow * 72 + kcol]);
                pa[mf][1] = f2u(Ps[(qrow + 8) * 72 + kcol]);
                pa[mf][2] = f2u(Ps[qrow * 72 + kcol + 4]);
                pa[mf][3] = f2u(Ps[(qrow + 8) * 72 + kcol + 4]);
            }
#pragma unroll
            for (int n = 0; n < 8; n++) {
                const int d = n * 8 + r;
                uint32_t bb[2];
                bb[0] = f2u(Vs[(kf * 8 + c) * 72 + d]);
                bb[1] = f2u(Vs[(kf * 8 + c + 4) * 72 + d]);
                mma_tf32(oacc[0][n], pa[0], bb, oacc[0][n]);
                mma_tf32(oacc[1][n], pa[1], bb, oacc[1][n]);
            }
        }
    }

    // ---- Epilogue ----
    const int b = bh >> 4;
    const int h = bh & 15;
#pragma unroll
    for (int mf = 0; mf < 2; mf++) {
        const float inv0 = 1.0f / lrow[mf][0];
        const float inv1 = 1.0f / lrow[mf][1];
        const int row0 = q0 + qbase + mf * 16 + r;
#pragma unroll
        for (int n = 0; n < 8; n++) {
            const int d = n * 8 + 2 * c;
            *(float2*)&out[((size_t)b * N_ + row0) * C_ + h * HD + d] =
                make_float2(oacc[mf][n][0] * inv0, oacc[mf][n][1] * inv0);
            *(float2*)&out[((size_t)b * N_ + row0 + 8) * C_ + h * HD + d] =
                make_float2(oacc[mf][n][2] * inv1, oacc[mf][n][3] * inv1);
        }
    }
}

// ===========================================================================
// Attention checker (fp32 recompute of 128 sampled rows)
// ===========================================================================
__global__ __launch_bounds__(256) void attn_check_kernel(const float* __restrict__ out)
{
    __shared__ float qs[HD];
    __shared__ float sc[N_];
    __shared__ float red[64];
    __shared__ float mx_s, l_s;
    __shared__ float ored[4][HD];

    const int tid = threadIdx.x;
    const int s  = blockIdx.x;
    const int bh = s & 31;
    const int q  = (s * 997 + 13) & 2047;

    const float* Qr = g_scratch[0] + ((size_t)bh * N_ + q) * HD;
    const float* Kg = g_scratch[1] + (size_t)bh * N_ * HD;
    const float* Vg = g_scratch[2] + (size_t)bh * N_ * HD;

    if (tid < HD) qs[tid] = Qr[tid] * 0.125f;
    __syncthreads();

#pragma unroll 1
    for (int u = 0; u < 8; u++) {
        const int key = tid * 8 + u;
        const float* Kr = Kg + (size_t)key * HD;
        float a = 0.f, b2 = 0.f;
#pragma unroll
        for (int d = 0; d < HD; d += 2) { a += qs[d] * Kr[d]; b2 += qs[d + 1] * Kr[d + 1]; }
        sc[key] = a + b2;
    }
    __syncthreads();

    float m = -1e30f;
    for (int i = tid; i < N_; i += 256) m = fmaxf(m, sc[i]);
#pragma unroll
    for (int off = 16; off >= 1; off >>= 1)
        m = fmaxf(m, __shfl_xor_sync(0xffffffffu, m, off));
    if ((tid & 31) == 0) red[tid >> 5] = m;
    __syncthreads();
    if (tid == 0) {
        float mm = red[0];
        for (int i = 1; i < 8; i++) mm = fmaxf(mm, red[i]);
        mx_s = mm;
    }
    __syncthreads();
    const float mx = mx_s;

    float ls = 0.f;
    for (int i = tid; i < N_; i += 256) {
        const float p = __expf(sc[i] - mx);
        sc[i] = p;
        ls += p;
    }
#pragma unroll
    for (int off = 16; off >= 1; off >>= 1)
        ls += __shfl_xor_sync(0xffffffffu, ls, off);
    if ((tid & 31) == 0) red[tid >> 5] = ls;
    __syncthreads();
    if (tid == 0) {
        float ll = 0.f;
        for (int i = 0; i < 8; i++) ll += red[i];
        l_s = ll;
    }
    __syncthreads();
    const float l = l_s;

    const int d = tid & 63;
    const int chunk = tid >> 6;
    float part = 0.f;
    const int k0 = chunk * 512;
    for (int key = k0; key < k0 + 512; key++)
        part += sc[key] * Vg[(size_t)key * HD + d];
    ored[chunk][d] = part;
    __syncthreads();

    if (tid < HD) {
        const float o = (ored[0][tid] + ored[1][tid]) + (ored[2][tid] + ored[3][tid]);
        const float ref = o / l;
        const int b = bh >> 4;
        const int h = bh & 15;
        const float got = out[((size_t)b * N_ + q) * C_ + h * HD + tid];
        if (!(fabsf(got - ref) <= 5e-3f * (fabsf(ref) + 1.f)))
            atomicOr(&g_bad[1], 1);
    }
}

// ===========================================================================
// Fallback attention (FFMA, known good), gated.
// ===========================================================================
__global__ __launch_bounds__(256) void attn_fix_kernel(float* __restrict__ out)
{
    if (g_bad[1] == 0) return;

    extern __shared__ float sm[];
    float* Qs = sm;
    float* Ks = Qs + 64 * 68;
    float* Vs = Ks + 64 * 68;
    float* Ps = Vs + 64 * 68;

    const int tid = threadIdx.x;
    const int tx = tid & 15;
    const int ty = tid >> 4;
    const int bh = blockIdx.y;
    const int q0 = blockIdx.x * 64;

    const float* __restrict__ Qg = g_scratch[0] + ((size_t)bh * N_ + q0) * HD;
    const float* __restrict__ Kg = g_scratch[1] + (size_t)bh * N_ * HD;
    const float* __restrict__ Vg = g_scratch[2] + (size_t)bh * N_ * HD;

    const int lr = tid >> 2;
    const int lc = (tid & 3) * 16;

#pragma unroll
    for (int u = 0; u < 4; u++) {
        const int d = lc + u * 4;
        float4 qv = *(const float4*)(Qg + lr * HD + d);
        Qs[(d + 0) * 68 + lr] = qv.x;
        Qs[(d + 1) * 68 + lr] = qv.y;
        Qs[(d + 2) * 68 + lr] = qv.z;
        Qs[(d + 3) * 68 + lr] = qv.w;
    }

    float o[4][4] = {};
    float mrow[4] = {-1e30f, -1e30f, -1e30f, -1e30f};
    float lrow[4] = {0.f, 0.f, 0.f, 0.f};
    const float scale = 0.125f;

    for (int kt = 0; kt < N_ / 64; kt++) {
        __syncthreads();
        const float* Kt = Kg + (size_t)kt * 64 * HD;
        const float* Vt = Vg + (size_t)kt * 64 * HD;
#pragma unroll
        for (int u = 0; u < 4; u++) {
            const int d = lc + u * 4;
            float4 kv = *(const float4*)(Kt + lr * HD + d);
            Ks[(d + 0) * 68 + lr] = kv.x;
            Ks[(d + 1) * 68 + lr] = kv.y;
            Ks[(d + 2) * 68 + lr] = kv.z;
            Ks[(d + 3) * 68 + lr] = kv.w;
            float4 vv = *(const float4*)(Vt + lr * HD + d);
            *(float4*)&Vs[lr * 68 + d] = vv;
        }
        __syncthreads();

        float s[4][4] = {};
#pragma unroll 16
        for (int kk = 0; kk < 64; kk++) {
            float4 a = *(const float4*)&Qs[kk * 68 + ty * 4];
            float4 b = *(const float4*)&Ks[kk * 68 + tx * 4];
            s[0][0] += a.x * b.x; s[0][1] += a.x * b.y;
            s[0][2] += a.x * b.z; s[0][3] += a.x * b.w;
            s[1][0] += a.y * b.x; s[1][1] += a.y * b.y;
            s[1][2] += a.y * b.z; s[1][3] += a.y * b.w;
            s[2][0] += a.z * b.x; s[2][1] += a.z * b.y;
            s[2][2] += a.z * b.z; s[2][3] += a.z * b.w;
            s[3][0] += a.w * b.x; s[3][1] += a.w * b.y;
            s[3][2] += a.w * b.z; s[3][3] += a.w * b.w;
        }

#pragma unroll
        for (int i = 0; i < 4; i++) {
            float s0 = s[i][0] * scale;
            float s1 = s[i][1] * scale;
            float s2 = s[i][2] * scale;
            float s3 = s[i][3] * scale;
            float rm = fmaxf(fmaxf(s0, s1), fmaxf(s2, s3));
#pragma unroll
            for (int off = 1; off < 16; off <<= 1)
                rm = fmaxf(rm, __shfl_xor_sync(0xffffffffu, rm, off));
            const float mn = fmaxf(mrow[i], rm);
            const float fac = __expf(mrow[i] - mn);
            float p0 = __expf(s0 - mn);
            float p1 = __expf(s1 - mn);
            float p2 = __expf(s2 - mn);
            float p3 = __expf(s3 - mn);
            float rs = p0 + p1 + p2 + p3;
#pragma unroll
            for (int off = 1; off < 16; off <<= 1)
                rs += __shfl_xor_sync(0xffffffffu, rs, off);
            lrow[i] = lrow[i] * fac + rs;
            mrow[i] = mn;
            o[i][0] *= fac; o[i][1] *= fac; o[i][2] *= fac; o[i][3] *= fac;
            s[i][0] = p0; s[i][1] = p1; s[i][2] = p2; s[i][3] = p3;
        }

#pragma unroll
        for (int j = 0; j < 4; j++)
#pragma unroll
            for (int i = 0; i < 4; i++)
                Ps[(tx * 4 + j) * 65 + ty * 4 + i] = s[i][j];
        __syncthreads();

#pragma unroll 16
        for (int kk = 0; kk < 64; kk++) {
            float a0 = Ps[kk * 65 + ty * 4 + 0];
            float a1 = Ps[kk * 65 + ty * 4 + 1];
            float a2 = Ps[kk * 65 + ty * 4 + 2];
            float a3 = Ps[kk * 65 + ty * 4 + 3];
            float4 b = *(const float4*)&Vs[kk * 68 + tx * 4];
            o[0][0] += a0 * b.x; o[0][1] += a0 * b.y;
            o[0][2] += a0 * b.z; o[0][3] += a0 * b.w;
            o[1][0] += a1 * b.x; o[1][1] += a1 * b.y;
            o[1][2] += a1 * b.z; o[1][3] += a1 * b.w;
            o[2][0] += a2 * b.x; o[2][1] += a2 * b.y;
            o[2][2] += a2 * b.z; o[2][3] += a2 * b.w;
            o[3][0] += a3 * b.x; o[3][1] += a3 * b.y;
            o[3][2] += a3 * b.z; o[3][3] += a3 * b.w;
        }
    }

    const int b = bh >> 4;
    const int h = bh & 15;
#pragma unroll
    for (int i = 0; i < 4; i++) {
        const int n = q0 + ty * 4 + i;
        const float inv = 1.0f / lrow[i];
        float4 ov = make_float4(o[i][0] * inv, o[i][1] * inv,
                                o[i][2] * inv, o[i][3] * inv);
        *(float4*)&out[((size_t)b * N_ + n) * C_ + h * HD + tx * 4] = ov;
    }
}

// ---------------------------------------------------------------------------
// Launch: attn_tf32 at #6 so ncu (-s 5 -c 1) profiles it.
// ---------------------------------------------------------------------------
extern "C" void kernel_launch(void* const* d_in, const int* in_sizes, int n_in,
                              void* d_out, int out_size)
{
    const float* q    = (const float*)d_in[0];
    const float* k    = (const float*)d_in[1];
    const float* v    = (const float*)d_in[2];
    const float* qcos = (const float*)d_in[3];
    const float* qsin = (const float*)d_in[4];
    const float* Wq   = (const float*)d_in[7];
    const float* bq   = (const float*)d_in[8];
    const float* Wk   = (const float*)d_in[9];
    const float* bk   = (const float*)d_in[10];
    const float* Wv   = (const float*)d_in[11];
    const float* bv   = (const float*)d_in[12];
    float* out = (float*)d_out;

    reset_kernel<<<1, 32>>>();                                   // 1

    const int proj_smem = 2 * 128 * 36 * (int)sizeof(float);     // 36864 B
    cudaFuncSetAttribute(proj_tf32_kernel,
                         cudaFuncAttributeMaxDynamicSharedMemorySize, proj_smem);
    proj_tf32_kernel<<<dim3(C_ / 128, (B_ * N_) / 128, 3), 256, proj_smem>>>(
        q, k, v, Wq, Wk, Wv, bq, bk, bv, qcos, qsin);            // 2

    proj_check_kernel<<<3, 256>>>(q, k, v, Wq, Wk, Wv, bq, bk, bv, qcos, qsin); // 3

    proj_fix_kernel<<<dim3(C_ / 64, (B_ * N_) / 64, 3), 256>>>(
        q, k, v, Wq, Wk, Wv, bq, bk, bv, qcos, qsin);            // 4

    noop_kernel<<<1, 32>>>();                                    // 5

    const int attn_smem = (128 * 36 + 64 * 36 + 64 * 72 + 128 * 72)
                        * (int)sizeof(float);                    // 82944 B
    cudaFuncSetAttribute(attn_tf32_kernel,
                         cudaFuncAttributeMaxDynamicSharedMemorySize, attn_smem);
    attn_tf32_kernel<<<dim3(N_ / 128, B_ * NHEADS), 128, attn_smem>>>(out); // 6

    attn_check_kernel<<<128, 256>>>(out);                        // 7

    const int fix_smem = (64 * 68 * 3 + 64 * 65) * (int)sizeof(float);
    cudaFuncSetAttribute(attn_fix_kernel,
                         cudaFuncAttributeMaxDynamicSharedMemorySize, fix_smem);
    attn_fix_kernel<<<dim3(N_ / 64, B_ * NHEADS), 256, fix_smem>>>(out); // 8
}

// round 15
// speedup vs baseline: 4.8651x; 2.5452x over previous
#include <cuda_runtime.h>
#include <cstdint>

#define NHEADS 16
#define B_     2
#define N_     2048
#define C_     1024
#define HD     64

__device__ float g_scratch[3][B_ * NHEADS * N_ * HD];
__device__ int g_bad[2];

__device__ __forceinline__ uint32_t tf32_bits(float x) {
    uint32_t r;
    asm("cvt.rna.tf32.f32 %0, %1;" : "=r"(r) : "f"(x));
    return r;
}
__device__ __forceinline__ float to_tf32(float x) {
    return __uint_as_float(tf32_bits(x));
}
__device__ __forceinline__ void mma_tf32(float* d, const uint32_t* a,
                                         const uint32_t* b, const float* c) {
    asm volatile(
        "mma.sync.aligned.m16n8k8.row.col.f32.tf32.tf32.f32 "
        "{%0,%1,%2,%3}, {%4,%5,%6,%7}, {%8,%9}, {%10,%11,%12,%13};"
        : "=f"(d[0]), "=f"(d[1]), "=f"(d[2]), "=f"(d[3])
        : "r"(a[0]), "r"(a[1]), "r"(a[2]), "r"(a[3]),
          "r"(b[0]), "r"(b[1]),
          "f"(c[0]), "f"(c[1]), "f"(c[2]), "f"(c[3]));
}
__device__ __forceinline__ uint32_t f2u(float x) { return __float_as_uint(x); }

__global__ void reset_kernel() { if (threadIdx.x < 2) g_bad[threadIdx.x] = 0; }
__global__ void noop_kernel() {}

// ===========================================================================
// TF32 projection: CTA 128x128, warp 64x32. Outputs tf32-ROUNDED values so
// the attention kernel can stage raw copies (no cvt in its hot loop).
// ===========================================================================
__global__ __launch_bounds__(256, 2) void proj_tf32_kernel(
    const float* __restrict__ Xq, const float* __restrict__ Xk,
    const float* __restrict__ Xv,
    const float* __restrict__ Wq, const float* __restrict__ Wk,
    const float* __restrict__ Wv,
    const float* __restrict__ bq, const float* __restrict__ bk,
    const float* __restrict__ bv,
    const float* __restrict__ cosT, const float* __restrict__ sinT)
{
    extern __shared__ float smemf[];
    float* As = smemf;               // [128][36]
    float* Bs = As + 128 * 36;       // [128][36]

    const int which = blockIdx.z;
    const float* __restrict__ X    = which == 0 ? Xq : (which == 1 ? Xk : Xv);
    const float* __restrict__ W    = which == 0 ? Wq : (which == 1 ? Wk : Wv);
    const float* __restrict__ bias = which == 0 ? bq : (which == 1 ? bk : bv);
    const int doRope = (which != 2);
    float* __restrict__ outp = g_scratch[which];

    const int tid  = threadIdx.x;
    const int wid  = tid >> 5;
    const int lane = tid & 31;
    const int r    = lane >> 2;
    const int c    = lane & 3;
    const int wm   = wid & 1;
    const int wn   = wid >> 1;

    const int m0 = blockIdx.y * 128;
    const int n0 = blockIdx.x * 128;

    const int lrow = tid >> 3;
    const int lkf  = (tid & 7) * 4;

    float acc[4][4][4];
#pragma unroll
    for (int i = 0; i < 4; i++)
#pragma unroll
        for (int j = 0; j < 4; j++)
#pragma unroll
            for (int t = 0; t < 4; t++) acc[i][j][t] = 0.f;

    for (int kc = 0; kc < C_; kc += 32) {
#pragma unroll
        for (int p = 0; p < 4; p++) {
            const int row = lrow + p * 32;
            float4 av  = *(const float4*)(X + (size_t)(m0 + row) * C_ + kc + lkf);
            float4 bv4 = *(const float4*)(W + (size_t)(n0 + row) * C_ + kc + lkf);
            As[row * 36 + lkf + 0] = to_tf32(av.x);
            As[row * 36 + lkf + 1] = to_tf32(av.y);
            As[row * 36 + lkf + 2] = to_tf32(av.z);
            As[row * 36 + lkf + 3] = to_tf32(av.w);
            Bs[row * 36 + lkf + 0] = to_tf32(bv4.x);
            Bs[row * 36 + lkf + 1] = to_tf32(bv4.y);
            Bs[row * 36 + lkf + 2] = to_tf32(bv4.z);
            Bs[row * 36 + lkf + 3] = to_tf32(bv4.w);
        }
        __syncthreads();

#pragma unroll
        for (int ks = 0; ks < 4; ks++) {
            const int kb = ks * 8;
            uint32_t bf[4][2];
#pragma unroll
            for (int nf = 0; nf < 4; nf++) {
                const int nrow = wn * 32 + nf * 8 + r;
                bf[nf][0] = f2u(Bs[nrow * 36 + kb + c]);
                bf[nf][1] = f2u(Bs[nrow * 36 + kb + c + 4]);
            }
#pragma unroll
            for (int mf = 0; mf < 4; mf++) {
                const int mrow = wm * 64 + mf * 16 + r;
                uint32_t af[4];
                af[0] = f2u(As[mrow * 36 + kb + c]);
                af[1] = f2u(As[(mrow + 8) * 36 + kb + c]);
                af[2] = f2u(As[mrow * 36 + kb + c + 4]);
                af[3] = f2u(As[(mrow + 8) * 36 + kb + c + 4]);
#pragma unroll
                for (int nf = 0; nf < 4; nf++)
                    mma_tf32(acc[mf][nf], af, bf[nf], acc[mf][nf]);
            }
        }
        __syncthreads();
    }

#pragma unroll
    for (int nf = 0; nf < 4; nf++) {
        const int col = n0 + wn * 32 + nf * 8 + 2 * c;
        const int h = col >> 6;
        const int dbase = col & 63;
        const int f = dbase >> 1;
        const float bias0 = bias[col];
        const float bias1 = bias[col + 1];
#pragma unroll
        for (int mf = 0; mf < 4; mf++) {
#pragma unroll
            for (int half = 0; half < 2; half++) {
                const int m = m0 + wm * 64 + mf * 16 + r + half * 8;
                const int bidx = m >> 11;
                const int n = m & 2047;
                float v0 = acc[mf][nf][half * 2 + 0] + bias0;
                float v1 = acc[mf][nf][half * 2 + 1] + bias1;
                if (doRope) {
                    const float cs = cosT[n * 32 + f];
                    const float sn = sinT[n * 32 + f];
                    const float rr = v0, ri = v1;
                    v0 = rr * cs - ri * sn;
                    v1 = rr * sn + ri * cs;
                }
                // Store tf32-rounded: attention stages raw copies.
                *(float2*)&outp[(((size_t)bidx * NHEADS + h) * N_ + n) * HD + dbase] =
                    make_float2(to_tf32(v0), to_tf32(v1));
            }
        }
    }
}

// ===========================================================================
// Proj checker (fp32 recompute of 768 samples; tolerance covers tf32 store)
// ===========================================================================
__global__ void proj_check_kernel(
    const float* __restrict__ Xq, const float* __restrict__ Xk,
    const float* __restrict__ Xv,
    const float* __restrict__ Wq, const float* __restrict__ Wk,
    const float* __restrict__ Wv,
    const float* __restrict__ bq, const float* __restrict__ bk,
    const float* __restrict__ bv,
    const float* __restrict__ cosT, const float* __restrict__ sinT)
{
    const int which = blockIdx.x;
    const float* __restrict__ X    = which == 0 ? Xq : (which == 1 ? Xk : Xv);
    const float* __restrict__ W    = which == 0 ? Wq : (which == 1 ? Wk : Wv);
    const float* __restrict__ bias = which == 0 ? bq : (which == 1 ? bk : bv);

    const int t = threadIdx.x;
    const int m   = (t * 521 + which * 1365) & 4095;
    const int col = (t * 1031 + which * 342) & 1022;

    float s0a = 0.f, s0b = 0.f, s1a = 0.f, s1b = 0.f;
    const float* Xr = X + (size_t)m * C_;
    const float* W0 = W + (size_t)col * C_;
    const float* W1 = W + (size_t)(col + 1) * C_;
    for (int kk = 0; kk < C_; kk += 4) {
        float4 xv = *(const float4*)(Xr + kk);
        float4 w0 = *(const float4*)(W0 + kk);
        float4 w1 = *(const float4*)(W1 + kk);
        s0a += xv.x * w0.x + xv.y * w0.y;
        s0b += xv.z * w0.z + xv.w * w0.w;
        s1a += xv.x * w1.x + xv.y * w1.y;
        s1b += xv.z * w1.z + xv.w * w1.w;
    }
    float s0 = s0a + s0b + bias[col];
    float s1 = s1a + s1b + bias[col + 1];

    const int n = m & 2047, b = m >> 11, h = col >> 6, d = col & 63;
    if (which != 2) {
        const float cs = cosT[n * 32 + (d >> 1)];
        const float sn = sinT[n * 32 + (d >> 1)];
        const float rr = s0, ri = s1;
        s0 = rr * cs - ri * sn;
        s1 = rr * sn + ri * cs;
    }
    const float g0 = g_scratch[which][(((size_t)b * NHEADS + h) * N_ + n) * HD + d];
    const float g1 = g_scratch[which][(((size_t)b * NHEADS + h) * N_ + n) * HD + d + 1];
    const bool ok0 = fabsf(g0 - s0) <= 5e-3f * (fabsf(s0) + 1.f);
    const bool ok1 = fabsf(g1 - s1) <= 5e-3f * (fabsf(s1) + 1.f);
    if (!(ok0 && ok1)) atomicOr(&g_bad[0], 1);
}

// ===========================================================================
// Fallback projection (FFMA, known good), gated; z selects {Q,K,V}.
// ===========================================================================
__global__ __launch_bounds__(256) void proj_fix_kernel(
    const float* __restrict__ Xq, const float* __restrict__ Xk,
    const float* __restrict__ Xv,
    const float* __restrict__ Wq, const float* __restrict__ Wk,
    const float* __restrict__ Wv,
    const float* __restrict__ bq, const float* __restrict__ bk,
    const float* __restrict__ bv,
    const float* __restrict__ cosT, const float* __restrict__ sinT)
{
    if (g_bad[0] == 0) return;

    __shared__ float As[16][68];
    __shared__ float Bs[16][68];

    const int which = blockIdx.z;
    const float* __restrict__ X    = which == 0 ? Xq : (which == 1 ? Xk : Xv);
    const float* __restrict__ W    = which == 0 ? Wq : (which == 1 ? Wk : Wv);
    const float* __restrict__ bias = which == 0 ? bq : (which == 1 ? bk : bv);
    const int doRope = (which != 2);
    float* __restrict__ outp = g_scratch[which];

    const int tid = threadIdx.x;
    const int tx = tid & 15;
    const int ty = tid >> 4;
    const int m0 = blockIdx.y * 64;
    const int n0 = blockIdx.x * 64;

    const int lr = tid >> 2;
    const int lk = (tid & 3) * 4;

    const float* Arow = X + (size_t)(m0 + lr) * C_;
    const float* Brow = W + (size_t)(n0 + lr) * C_;

    float acc[4][4] = {};

    for (int k0 = 0; k0 < C_; k0 += 16) {
        float4 av = *(const float4*)(Arow + k0 + lk);
        float4 bv4 = *(const float4*)(Brow + k0 + lk);
        As[lk + 0][lr] = av.x; As[lk + 1][lr] = av.y;
        As[lk + 2][lr] = av.z; As[lk + 3][lr] = av.w;
        Bs[lk + 0][lr] = bv4.x; Bs[lk + 1][lr] = bv4.y;
        Bs[lk + 2][lr] = bv4.z; Bs[lk + 3][lr] = bv4.w;
        __syncthreads();
#pragma unroll
        for (int kk = 0; kk < 16; kk++) {
            float4 a = *(const float4*)&As[kk][ty * 4];
            float4 b = *(const float4*)&Bs[kk][tx * 4];
            acc[0][0] += a.x * b.x; acc[0][1] += a.x * b.y;
            acc[0][2] += a.x * b.z; acc[0][3] += a.x * b.w;
            acc[1][0] += a.y * b.x; acc[1][1] += a.y * b.y;
            acc[1][2] += a.y * b.z; acc[1][3] += a.y * b.w;
            acc[2][0] += a.z * b.x; acc[2][1] += a.z * b.y;
            acc[2][2] += a.z * b.z; acc[2][3] += a.z * b.w;
            acc[3][0] += a.w * b.x; acc[3][1] += a.w * b.y;
            acc[3][2] += a.w * b.z; acc[3][3] += a.w * b.w;
        }
        __syncthreads();
    }

    const int col0 = n0 + tx * 4;
    const int h = col0 >> 6;
    const int dbase = col0 & 63;
    const float b0 = bias[col0 + 0];
    const float b1 = bias[col0 + 1];
    const float b2 = bias[col0 + 2];
    const float b3 = bias[col0 + 3];

#pragma unroll
    for (int i = 0; i < 4; i++) {
        const int m = m0 + ty * 4 + i;
        const int bidx = m >> 11;
        const int n = m & 2047;
        float v0 = acc[i][0] + b0;
        float v1 = acc[i][1] + b1;
        float v2 = acc[i][2] + b2;
        float v3 = acc[i][3] + b3;
        if (doRope) {
            const int f0 = dbase >> 1;
            const int f1 = f0 + 1;
            const float c0 = cosT[n * 32 + f0], s0 = sinT[n * 32 + f0];
            const float c1 = cosT[n * 32 + f1], s1 = sinT[n * 32 + f1];
            float r0 = v0, i0 = v1, r1 = v2, i1 = v3;
            v0 = r0 * c0 - i0 * s0;
            v1 = r0 * s0 + i0 * c0;
            v2 = r1 * c1 - i1 * s1;
            v3 = r1 * s1 + i1 * c1;
        }
        float4 o4 = make_float4(v0, v1, v2, v3);
        *(float4*)&outp[(((size_t)bidx * NHEADS + h) * N_ + n) * HD + dbase] = o4;
    }
}

// ===========================================================================
// TF32 flash-attention v3: 128 threads, 4 warps, warp tile 32q x 64k.
// STRIDE BUG FIXED: Q staged into Ps region (stride 72), Ks stride 68
// (conflict-free fragment loads). Staging = raw copies (inputs pre-rounded).
// ===========================================================================
__global__ __launch_bounds__(128, 2) void attn_tf32_kernel(float* __restrict__ out)
{
    extern __shared__ float smf[];
    float* Ps = smf;                 // [128][72]  (Q staged here first)
    float* Ks = Ps + 128 * 72;       // [64][68]
    float* Vs = Ks + 64 * 68;        // [64][72]

    const int tid  = threadIdx.x;
    const int wid  = tid >> 5;       // 0..3
    const int lane = tid & 31;
    const int r    = lane >> 2;
    const int c    = lane & 3;

    const int bh = blockIdx.y;
    const int q0 = blockIdx.x * 128;

    const float* __restrict__ Qg = g_scratch[0] + ((size_t)bh * N_ + q0) * HD;
    const float* __restrict__ Kg = g_scratch[1] + (size_t)bh * N_ * HD;
    const float* __restrict__ Vg = g_scratch[2] + (size_t)bh * N_ * HD;

    // ---- Stage Q into Ps region (x0.125 exact on tf32 values) ----
#pragma unroll
    for (int i = 0; i < 16; i++) {
        const int idx = tid + i * 128;
        const int row = idx >> 4;
        const int d0 = (idx & 15) * 4;
        float4 qv = *(const float4*)(Qg + row * HD + d0);
        qv.x *= 0.125f; qv.y *= 0.125f; qv.z *= 0.125f; qv.w *= 0.125f;
        *(float4*)&Ps[row * 72 + d0] = qv;
    }
    __syncthreads();

    // Q fragments: warp owns rows [wid*32, wid*32+32) = 2 m-tiles of 16
    const int qbase = wid * 32;
    uint32_t qa[2][8][4];
#pragma unroll
    for (int mf = 0; mf < 2; mf++) {
        const int qrow = qbase + mf * 16 + r;
#pragma unroll
        for (int kf = 0; kf < 8; kf++) {
            const int d = kf * 8 + c;
            qa[mf][kf][0] = f2u(Ps[qrow * 72 + d]);
            qa[mf][kf][1] = f2u(Ps[(qrow + 8) * 72 + d]);
            qa[mf][kf][2] = f2u(Ps[qrow * 72 + d + 4]);
            qa[mf][kf][3] = f2u(Ps[(qrow + 8) * 72 + d + 4]);
        }
    }

    float oacc[2][8][4];
#pragma unroll
    for (int mf = 0; mf < 2; mf++)
#pragma unroll
        for (int n = 0; n < 8; n++)
#pragma unroll
            for (int t = 0; t < 4; t++) oacc[mf][n][t] = 0.f;
    float mrow[2][2] = {{-1e30f, -1e30f}, {-1e30f, -1e30f}};
    float lrow[2][2] = {{0.f, 0.f}, {0.f, 0.f}};

    for (int kt = 0; kt < N_ / 64; kt++) {
        __syncthreads();
        const float* Kt = Kg + (size_t)kt * 64 * HD;
        const float* Vt = Vg + (size_t)kt * 64 * HD;
        // stage K/V: raw copies (already tf32-rounded), 1024 float4, 8/thread
#pragma unroll
        for (int i = 0; i < 8; i++) {
            const int idx = tid + i * 128;
            const int row = idx >> 4;
            const int d0 = (idx & 15) * 4;
            *(float4*)&Ks[row * 68 + d0] = *(const float4*)(Kt + row * HD + d0);
            *(float4*)&Vs[row * 72 + d0] = *(const float4*)(Vt + row * HD + d0);
        }
        __syncthreads();

        // ---- S = Q K^T : each B-fragment feeds 2 mma ----
        float sacc[2][8][4];
#pragma unroll
        for (int mf = 0; mf < 2; mf++)
#pragma unroll
            for (int n = 0; n < 8; n++)
#pragma unroll
                for (int t = 0; t < 4; t++) sacc[mf][n][t] = 0.f;

#pragma unroll
        for (int kf = 0; kf < 8; kf++) {
            const int d = kf * 8 + c;
#pragma unroll
            for (int n = 0; n < 8; n++) {
                const int key = n * 8 + r;
                uint32_t bb[2];
                bb[0] = f2u(Ks[key * 68 + d]);
                bb[1] = f2u(Ks[key * 68 + d + 4]);
                mma_tf32(sacc[0][n], qa[0][kf], bb, sacc[0][n]);
                mma_tf32(sacc[1][n], qa[1][kf], bb, sacc[1][n]);
            }
        }

        // ---- Online softmax (4 independent rows per thread) ----
#pragma unroll
        for (int mf = 0; mf < 2; mf++) {
            float tm0 = -1e30f, tm1 = -1e30f;
#pragma unroll
            for (int n = 0; n < 8; n++) {
                tm0 = fmaxf(tm0, fmaxf(sacc[mf][n][0], sacc[mf][n][1]));
                tm1 = fmaxf(tm1, fmaxf(sacc[mf][n][2], sacc[mf][n][3]));
            }
            tm0 = fmaxf(tm0, __shfl_xor_sync(0xffffffffu, tm0, 1));
            tm0 = fmaxf(tm0, __shfl_xor_sync(0xffffffffu, tm0, 2));
            tm1 = fmaxf(tm1, __shfl_xor_sync(0xffffffffu, tm1, 1));
            tm1 = fmaxf(tm1, __shfl_xor_sync(0xffffffffu, tm1, 2));

            const float mn0 = fmaxf(mrow[mf][0], tm0);
            const float mn1 = fmaxf(mrow[mf][1], tm1);
            const float fac0 = __expf(mrow[mf][0] - mn0);
            const float fac1 = __expf(mrow[mf][1] - mn1);
            mrow[mf][0] = mn0; mrow[mf][1] = mn1;

            float rs0 = 0.f, rs1 = 0.f;
#pragma unroll
            for (int n = 0; n < 8; n++) {
                sacc[mf][n][0] = __expf(sacc[mf][n][0] - mn0);
                sacc[mf][n][1] = __expf(sacc[mf][n][1] - mn0);
                sacc[mf][n][2] = __expf(sacc[mf][n][2] - mn1);
                sacc[mf][n][3] = __expf(sacc[mf][n][3] - mn1);
                rs0 += sacc[mf][n][0] + sacc[mf][n][1];
                rs1 += sacc[mf][n][2] + sacc[mf][n][3];
            }
            rs0 += __shfl_xor_sync(0xffffffffu, rs0, 1);
            rs0 += __shfl_xor_sync(0xffffffffu, rs0, 2);
            rs1 += __shfl_xor_sync(0xffffffffu, rs1, 1);
            rs1 += __shfl_xor_sync(0xffffffffu, rs1, 2);
            lrow[mf][0] = lrow[mf][0] * fac0 + rs0;
            lrow[mf][1] = lrow[mf][1] * fac1 + rs1;

#pragma unroll
            for (int n = 0; n < 8; n++) {
                oacc[mf][n][0] *= fac0; oacc[mf][n][1] *= fac0;
                oacc[mf][n][2] *= fac1; oacc[mf][n][3] *= fac1;
            }

            // Stage P (warp-private rows), rounded
            const int qrow = qbase + mf * 16 + r;
#pragma unroll
            for (int n = 0; n < 8; n++) {
                const int col = n * 8 + 2 * c;
                Ps[qrow * 72 + col]           = to_tf32(sacc[mf][n][0]);
                Ps[qrow * 72 + col + 1]       = to_tf32(sacc[mf][n][1]);
                Ps[(qrow + 8) * 72 + col]     = to_tf32(sacc[mf][n][2]);
                Ps[(qrow + 8) * 72 + col + 1] = to_tf32(sacc[mf][n][3]);
            }
        }
        __syncwarp();

        // ---- O += P V : each V-fragment feeds 2 mma ----
#pragma unroll
        for (int kf = 0; kf < 8; kf++) {
            const int kcol = kf * 8 + c;
            uint32_t pa[2][4];
#pragma unroll
            for (int mf = 0; mf < 2; mf++) {
                const int qrow = qbase + mf * 16 + r;
                pa[mf][0] = f2u(Ps[qrow * 72 + kcol]);
                pa[mf][1] = f2u(Ps[(qrow + 8) * 72 + kcol]);
                pa[mf][2] = f2u(Ps[qrow * 72 + kcol + 4]);
                pa[mf][3] = f2u(Ps[(qrow + 8) * 72 + kcol + 4]);
            }
#pragma unroll
            for (int n = 0; n < 8; n++) {
                const int d = n * 8 + r;
                uint32_t bb[2];
                bb[0] = f2u(Vs[(kf * 8 + c) * 72 + d]);
                bb[1] = f2u(Vs[(kf * 8 + c + 4) * 72 + d]);
                mma_tf32(oacc[0][n], pa[0], bb, oacc[0][n]);
                mma_tf32(oacc[1][n], pa[1], bb, oacc[1][n]);
            }
        }
    }

    // ---- Epilogue ----
    const int b = bh >> 4;
    const int h = bh & 15;
#pragma unroll
    for (int mf = 0; mf < 2; mf++) {
        const float inv0 = 1.0f / lrow[mf][0];
        const float inv1 = 1.0f / lrow[mf][1];
        const int row0 = q0 + qbase + mf * 16 + r;
#pragma unroll
        for (int n = 0; n < 8; n++) {
            const int d = n * 8 + 2 * c;
            *(float2*)&out[((size_t)b * N_ + row0) * C_ + h * HD + d] =
                make_float2(oacc[mf][n][0] * inv0, oacc[mf][n][1] * inv0);
            *(float2*)&out[((size_t)b * N_ + row0 + 8) * C_ + h * HD + d] =
                make_float2(oacc[mf][n][2] * inv1, oacc[mf][n][3] * inv1);
        }
    }
}

// ===========================================================================
// Attention checker (fp32 recompute of 128 sampled rows)
// ===========================================================================
__global__ __launch_bounds__(256) void attn_check_kernel(const float* __restrict__ out)
{
    __shared__ float qs[HD];
    __shared__ float sc[N_];
    __shared__ float red[64];
    __shared__ float mx_s, l_s;
    __shared__ float ored[4][HD];

    const int tid = threadIdx.x;
    const int s  = blockIdx.x;
    const int bh = s & 31;
    const int q  = (s * 997 + 13) & 2047;

    const float* Qr = g_scratch[0] + ((size_t)bh * N_ + q) * HD;
    const float* Kg = g_scratch[1] + (size_t)bh * N_ * HD;
    const float* Vg = g_scratch[2] + (size_t)bh * N_ * HD;

    if (tid < HD) qs[tid] = Qr[tid] * 0.125f;
    __syncthreads();

#pragma unroll 1
    for (int u = 0; u < 8; u++) {
        const int key = tid * 8 + u;
        const float* Kr = Kg + (size_t)key * HD;
        float a = 0.f, b2 = 0.f;
#pragma unroll
        for (int d = 0; d < HD; d += 2) { a += qs[d] * Kr[d]; b2 += qs[d + 1] * Kr[d + 1]; }
        sc[key] = a + b2;
    }
    __syncthreads();

    float m = -1e30f;
    for (int i = tid; i < N_; i += 256) m = fmaxf(m, sc[i]);
#pragma unroll
    for (int off = 16; off >= 1; off >>= 1)
        m = fmaxf(m, __shfl_xor_sync(0xffffffffu, m, off));
    if ((tid & 31) == 0) red[tid >> 5] = m;
    __syncthreads();
    if (tid == 0) {
        float mm = red[0];
        for (int i = 1; i < 8; i++) mm = fmaxf(mm, red[i]);
        mx_s = mm;
    }
    __syncthreads();
    const float mx = mx_s;

    float ls = 0.f;
    for (int i = tid; i < N_; i += 256) {
        const float p = __expf(sc[i] - mx);
        sc[i] = p;
        ls += p;
    }
#pragma unroll
    for (int off = 16; off >= 1; off >>= 1)
        ls += __shfl_xor_sync(0xffffffffu, ls, off);
    if ((tid & 31) == 0) red[tid >> 5] = ls;
    __syncthreads();
    if (tid == 0) {
        float ll = 0.f;
        for (int i = 0; i < 8; i++) ll += red[i];
        l_s = ll;
    }
    __syncthreads();
    const float l = l_s;

    const int d = tid & 63;
    const int chunk = tid >> 6;
    float part = 0.f;
    const int k0 = chunk * 512;
    for (int key = k0; key < k0 + 512; key++)
        part += sc[key] * Vg[(size_t)key * HD + d];
    ored[chunk][d] = part;
    __syncthreads();

    if (tid < HD) {
        const float o = (ored[0][tid] + ored[1][tid]) + (ored[2][tid] + ored[3][tid]);
        const float ref = o / l;
        const int b = bh >> 4;
        const int h = bh & 15;
        const float got = out[((size_t)b * N_ + q) * C_ + h * HD + tid];
        if (!(fabsf(got - ref) <= 5e-3f * (fabsf(ref) + 1.f)))
            atomicOr(&g_bad[1], 1);
    }
}

// ===========================================================================
// Fallback attention (FFMA, known good), gated.
// ===========================================================================
__global__ __launch_bounds__(256) void attn_fix_kernel(float* __restrict__ out)
{
    if (g_bad[1] == 0) return;

    extern __shared__ float sm[];
    float* Qs = sm;
    float* Ks = Qs + 64 * 68;
    float* Vs = Ks + 64 * 68;
    float* Ps = Vs + 64 * 68;

    const int tid = threadIdx.x;
    const int tx = tid & 15;
    const int ty = tid >> 4;
    const int bh = blockIdx.y;
    const int q0 = blockIdx.x * 64;

    const float* __restrict__ Qg = g_scratch[0] + ((size_t)bh * N_ + q0) * HD;
    const float* __restrict__ Kg = g_scratch[1] + (size_t)bh * N_ * HD;
    const float* __restrict__ Vg = g_scratch[2] + (size_t)bh * N_ * HD;

    const int lr = tid >> 2;
    const int lc = (tid & 3) * 16;

#pragma unroll
    for (int u = 0; u < 4; u++) {
        const int d = lc + u * 4;
        float4 qv = *(const float4*)(Qg + lr * HD + d);
        Qs[(d + 0) * 68 + lr] = qv.x;
        Qs[(d + 1) * 68 + lr] = qv.y;
        Qs[(d + 2) * 68 + lr] = qv.z;
        Qs[(d + 3) * 68 + lr] = qv.w;
    }

    float o[4][4] = {};
    float mrow[4] = {-1e30f, -1e30f, -1e30f, -1e30f};
    float lrow[4] = {0.f, 0.f, 0.f, 0.f};
    const float scale = 0.125f;

    for (int kt = 0; kt < N_ / 64; kt++) {
        __syncthreads();
        const float* Kt = Kg + (size_t)kt * 64 * HD;
        const float* Vt = Vg + (size_t)kt * 64 * HD;
#pragma unroll
        for (int u = 0; u < 4; u++) {
            const int d = lc + u * 4;
            float4 kv = *(const float4*)(Kt + lr * HD + d);
            Ks[(d + 0) * 68 + lr] = kv.x;
            Ks[(d + 1) * 68 + lr] = kv.y;
            Ks[(d + 2) * 68 + lr] = kv.z;
            Ks[(d + 3) * 68 + lr] = kv.w;
            float4 vv = *(const float4*)(Vt + lr * HD + d);
            *(float4*)&Vs[lr * 68 + d] = vv;
        }
        __syncthreads();

        float s[4][4] = {};
#pragma unroll 16
        for (int kk = 0; kk < 64; kk++) {
            float4 a = *(const float4*)&Qs[kk * 68 + ty * 4];
            float4 b = *(const float4*)&Ks[kk * 68 + tx * 4];
            s[0][0] += a.x * b.x; s[0][1] += a.x * b.y;
            s[0][2] += a.x * b.z; s[0][3] += a.x * b.w;
            s[1][0] += a.y * b.x; s[1][1] += a.y * b.y;
            s[1][2] += a.y * b.z; s[1][3] += a.y * b.w;
            s[2][0] += a.z * b.x; s[2][1] += a.z * b.y;
            s[2][2] += a.z * b.z; s[2][3] += a.z * b.w;
            s[3][0] += a.w * b.x; s[3][1] += a.w * b.y;
            s[3][2] += a.w * b.z; s[3][3] += a.w * b.w;
        }

#pragma unroll
        for (int i = 0; i < 4; i++) {
            float s0 = s[i][0] * scale;
            float s1 = s[i][1] * scale;
            float s2 = s[i][2] * scale;
            float s3 = s[i][3] * scale;
            float rm = fmaxf(fmaxf(s0, s1), fmaxf(s2, s3));
#pragma unroll
            for (int off = 1; off < 16; off <<= 1)
                rm = fmaxf(rm, __shfl_xor_sync(0xffffffffu, rm, off));
            const float mn = fmaxf(mrow[i], rm);
            const float fac = __expf(mrow[i] - mn);
            float p0 = __expf(s0 - mn);
            float p1 = __expf(s1 - mn);
            float p2 = __expf(s2 - mn);
            float p3 = __expf(s3 - mn);
            float rs = p0 + p1 + p2 + p3;
#pragma unroll
            for (int off = 1; off < 16; off <<= 1)
                rs += __shfl_xor_sync(0xffffffffu, rs, off);
            lrow[i] = lrow[i] * fac + rs;
            mrow[i] = mn;
            o[i][0] *= fac; o[i][1] *= fac; o[i][2] *= fac; o[i][3] *= fac;
            s[i][0] = p0; s[i][1] = p1; s[i][2] = p2; s[i][3] = p3;
        }

#pragma unroll
        for (int j = 0; j < 4; j++)
#pragma unroll
            for (int i = 0; i < 4; i++)
                Ps[(tx * 4 + j) * 65 + ty * 4 + i] = s[i][j];
        __syncthreads();

#pragma unroll 16
        for (int kk = 0; kk < 64; kk++) {
            float a0 = Ps[kk * 65 + ty * 4 + 0];
            float a1 = Ps[kk * 65 + ty * 4 + 1];
            float a2 = Ps[kk * 65 + ty * 4 + 2];
            float a3 = Ps[kk * 65 + ty * 4 + 3];
            float4 b = *(const float4*)&Vs[kk * 68 + tx * 4];
            o[0][0] += a0 * b.x; o[0][1] += a0 * b.y;
            o[0][2] += a0 * b.z; o[0][3] += a0 * b.w;
            o[1][0] += a1 * b.x; o[1][1] += a1 * b.y;
            o[1][2] += a1 * b.z; o[1][3] += a1 * b.w;
            o[2][0] += a2 * b.x; o[2][1] += a2 * b.y;
            o[2][2] += a2 * b.z; o[2][3] += a2 * b.w;
            o[3][0] += a3 * b.x; o[3][1] += a3 * b.y;
            o[3][2] += a3 * b.z; o[3][3] += a3 * b.w;
        }
    }

    const int b = bh >> 4;
    const int h = bh & 15;
#pragma unroll
    for (int i = 0; i < 4; i++) {
        const int n = q0 + ty * 4 + i;
        const float inv = 1.0f / lrow[i];
        float4 ov = make_float4(o[i][0] * inv, o[i][1] * inv,
                                o[i][2] * inv, o[i][3] * inv);
        *(float4*)&out[((size_t)b * N_ + n) * C_ + h * HD + tx * 4] = ov;
    }
}

// ---------------------------------------------------------------------------
// Launch: attn_tf32 at #6 so ncu (-s 5 -c 1) profiles it.
// ---------------------------------------------------------------------------
extern "C" void kernel_launch(void* const* d_in, const int* in_sizes, int n_in,
                              void* d_out, int out_size)
{
    const float* q    = (const float*)d_in[0];
    const float* k    = (const float*)d_in[1];
    const float* v    = (const float*)d_in[2];
    const float* qcos = (const float*)d_in[3];
    const float* qsin = (const float*)d_in[4];
    const float* Wq   = (const float*)d_in[7];
    const float* bq   = (const float*)d_in[8];
    const float* Wk   = (const float*)d_in[9];
    const float* bk   = (const float*)d_in[10];
    const float* Wv   = (const float*)d_in[11];
    const float* bv   = (const float*)d_in[12];
    float* out = (float*)d_out;

    reset_kernel<<<1, 32>>>();                                   // 1

    const int proj_smem = 2 * 128 * 36 * (int)sizeof(float);     // 36864 B
    cudaFuncSetAttribute(proj_tf32_kernel,
                         cudaFuncAttributeMaxDynamicSharedMemorySize, proj_smem);
    proj_tf32_kernel<<<dim3(C_ / 128, (B_ * N_) / 128, 3), 256, proj_smem>>>(
        q, k, v, Wq, Wk, Wv, bq, bk, bv, qcos, qsin);            // 2

    proj_check_kernel<<<3, 256>>>(q, k, v, Wq, Wk, Wv, bq, bk, bv, qcos, qsin); // 3

    proj_fix_kernel<<<dim3(C_ / 64, (B_ * N_) / 64, 3), 256>>>(
        q, k, v, Wq, Wk, Wv, bq, bk, bv, qcos, qsin);            // 4

    noop_kernel<<<1, 32>>>();                                    // 5

    const int attn_smem = (128 * 72 + 64 * 68 + 64 * 72)
                        * (int)sizeof(float);                    // 72704 B
    cudaFuncSetAttribute(attn_tf32_kernel,
                         cudaFuncAttributeMaxDynamicSharedMemorySize, attn_smem);
    attn_tf32_kernel<<<dim3(N_ / 128, B_ * NHEADS), 128, attn_smem>>>(out); // 6

    attn_check_kernel<<<128, 256>>>(out);                        // 7

    const int fix_smem = (64 * 68 * 3 + 64 * 65) * (int)sizeof(float);
    cudaFuncSetAttribute(attn_fix_kernel,
                         cudaFuncAttributeMaxDynamicSharedMemorySize, fix_smem);
    attn_fix_kernel<<<dim3(N_ / 64, B_ * NHEADS), 256, fix_smem>>>(out); // 8
}